// round 4
// baseline (speedup 1.0000x reference)
#include <cuda_runtime.h>

// Problem constants
#define B_  64
#define T_  256
#define E_  512
#define U_  1024
#define N3_ 3072

#define NBLK 128          // scan grid (1 block/SM, all resident -> barrier safe)
#define UPB  8            // GRU units per scan block (128*8 = 1024)
#define SCAN_THREADS 256  // 2 k-teams x (32 row-pairs x 4 col-groups)

// smem layout for k_scan (bytes)
#define OFF_WHS   0                      // [1024][24] u64 (w,w) pairs  = 196608
#define OFF_HC    196608                 // [2 teams][32*64] float      = 16384
#define OFF_RECS  212992                 // [2 teams][24*64] float      = 12288
#define OFF_BHS   225280                 // [32] float
#define SCAN_SMEM 225408

typedef unsigned long long u64;

// ----------------- device scratch (no allocations allowed) -----------------
__device__ float g_xproj[(size_t)B_ * T_ * N3_];  // [B*T][3U] incl. bx
__device__ float g_hT[2][U_ * B_];                // transposed h, double buffered
__device__ unsigned g_bar;

// ----------------- packed f32x2 helpers ------------------------------------
__device__ __forceinline__ u64 pack2(float lo, float hi) {
    u64 r;
    asm("mov.b64 %0, {%1, %2};" : "=l"(r)
        : "r"(__float_as_uint(lo)), "r"(__float_as_uint(hi)));
    return r;
}
__device__ __forceinline__ void unpack2(u64 v, float& lo, float& hi) {
    unsigned a, b;
    asm("mov.b64 {%0, %1}, %2;" : "=r"(a), "=r"(b) : "l"(v));
    lo = __uint_as_float(a);
    hi = __uint_as_float(b);
}
__device__ __forceinline__ u64 fma2(u64 a, u64 b, u64 c) {
    u64 d;
    asm("fma.rn.f32x2 %0, %1, %2, %3;" : "=l"(d) : "l"(a), "l"(b), "l"(c));
    return d;
}

// ----------------- init: reset barrier + transpose h0 ----------------------
__global__ void k_init(const float* __restrict__ hidden) {
    int idx = blockIdx.x * blockDim.x + threadIdx.x;
    if (idx == 0) g_bar = 0u;
    if (idx < B_ * U_) {
        int m = idx >> 10;        // batch row
        int k = idx & (U_ - 1);   // unit
        g_hT[0][k * B_ + m] = hidden[idx];
    }
}

// ----------------- kernel 1: x_proj = emb[tokens] @ Wx + bx ----------------
// 128x128 tile, KB=16, 256 threads, 8x8 micro via f32x2.
__global__ __launch_bounds__(256, 2)
void k_xproj(const int* __restrict__ tokens, const float* __restrict__ emb,
             const float* __restrict__ Wx, const float* __restrict__ bx) {
    __shared__ float As[16][132];   // [k][row] (A transposed)
    __shared__ float Bs[16][132];   // [k][col]
    __shared__ int toks[128];

    const int tid = threadIdx.x;
    const int n0 = blockIdx.x * 128;
    const int m0 = blockIdx.y * 128;

    if (tid < 128) toks[tid] = tokens[m0 + tid];

    const int tx = tid & 15;   // col group: cols tx*4..+3 and 64+tx*4..+3
    const int ty = tid >> 4;   // row group: rows ty*4..+3 and 64+ty*4..+3

    u64 acc[4][8];
#pragma unroll
    for (int g = 0; g < 4; g++)
#pragma unroll
        for (int j = 0; j < 8; j++) acc[g][j] = 0ull;

    for (int k0 = 0; k0 < E_; k0 += 16) {
        __syncthreads();
        // load A tile: 128 rows x 16 k, gathered through embedding
#pragma unroll
        for (int q0 = 0; q0 < 2; q0++) {
            int q = tid + q0 * 256;            // 0..511 float4s
            int row = q >> 2;
            int kb = (q & 3) << 2;
            const float4 av = *reinterpret_cast<const float4*>(
                &emb[(size_t)toks[row] * E_ + k0 + kb]);
            As[kb + 0][row] = av.x;
            As[kb + 1][row] = av.y;
            As[kb + 2][row] = av.z;
            As[kb + 3][row] = av.w;
        }
        // load B tile: 16 k x 128 cols
#pragma unroll
        for (int q0 = 0; q0 < 2; q0++) {
            int q = tid + q0 * 256;
            int kr = q >> 5;
            int nb = (q & 31) << 2;
            *reinterpret_cast<float4*>(&Bs[kr][nb]) =
                *reinterpret_cast<const float4*>(
                    &Wx[(size_t)(k0 + kr) * N3_ + n0 + nb]);
        }
        __syncthreads();

#pragma unroll
        for (int k = 0; k < 16; k++) {
            ulonglong2 a0 = *reinterpret_cast<const ulonglong2*>(&As[k][ty * 4]);
            ulonglong2 a1 = *reinterpret_cast<const ulonglong2*>(&As[k][64 + ty * 4]);
            float4 b0 = *reinterpret_cast<const float4*>(&Bs[k][tx * 4]);
            float4 b1 = *reinterpret_cast<const float4*>(&Bs[k][64 + tx * 4]);
            u64 ap[4] = {a0.x, a0.y, a1.x, a1.y};
            float bc[8] = {b0.x, b0.y, b0.z, b0.w, b1.x, b1.y, b1.z, b1.w};
#pragma unroll
            for (int j = 0; j < 8; j++) {
                u64 bp = pack2(bc[j], bc[j]);
#pragma unroll
                for (int g = 0; g < 4; g++) acc[g][j] = fma2(ap[g], bp, acc[g][j]);
            }
        }
    }

    // epilogue: add bias, store
    float bxv[8];
#pragma unroll
    for (int j = 0; j < 8; j++)
        bxv[j] = bx[n0 + ((j >> 2) ? 64 : 0) + tx * 4 + (j & 3)];

#pragma unroll
    for (int g = 0; g < 4; g++) {
        int r0 = ((g >> 1) << 6) + ty * 4 + ((g & 1) << 1);  // rows r0, r0+1
        float lo[8], hi[8];
#pragma unroll
        for (int j = 0; j < 8; j++) unpack2(acc[g][j], lo[j], hi[j]);
        float* p0 = &g_xproj[(size_t)(m0 + r0) * N3_ + n0];
        float* p1 = p0 + N3_;
        float4 v;
        v.x = lo[0] + bxv[0]; v.y = lo[1] + bxv[1];
        v.z = lo[2] + bxv[2]; v.w = lo[3] + bxv[3];
        *reinterpret_cast<float4*>(p0 + tx * 4) = v;
        v.x = lo[4] + bxv[4]; v.y = lo[5] + bxv[5];
        v.z = lo[6] + bxv[6]; v.w = lo[7] + bxv[7];
        *reinterpret_cast<float4*>(p0 + 64 + tx * 4) = v;
        v.x = hi[0] + bxv[0]; v.y = hi[1] + bxv[1];
        v.z = hi[2] + bxv[2]; v.w = hi[3] + bxv[3];
        *reinterpret_cast<float4*>(p1 + tx * 4) = v;
        v.x = hi[4] + bxv[4]; v.y = hi[5] + bxv[5];
        v.z = hi[6] + bxv[6]; v.w = hi[7] + bxv[7];
        *reinterpret_cast<float4*>(p1 + 64 + tx * 4) = v;
    }
}

// ----------------- kernel 2: persistent GRU scan ---------------------------
// 256 threads = 2 k-split teams of 128. Team layout: 32 row-pairs x 4
// col-groups; each thread computes 2 rows x 6 cols with f32x2 FMA.
// Teams process interleaved 32-k chunks; partial sums combined via smem.
__global__ __launch_bounds__(SCAN_THREADS, 1)
void k_scan(const float* __restrict__ Wh, const float* __restrict__ bh,
            float* __restrict__ out) {
    extern __shared__ char smem[];
    u64* whs2 = reinterpret_cast<u64*>(smem + OFF_WHS);       // [1024][24] (w,w)
    float* hc = reinterpret_cast<float*>(smem + OFF_HC);      // [2][32*64]
    float* recs = reinterpret_cast<float*>(smem + OFF_RECS);  // [2][24*64]
    float* bhs = reinterpret_cast<float*>(smem + OFF_BHS);    // [24]

    const int tid = threadIdx.x;
    const int u0 = blockIdx.x * UPB;
    const int team = tid >> 7;      // 0/1: k-split half
    const int ttid = tid & 127;
    const int rp = ttid >> 2;       // row pair: rows 2rp, 2rp+1
    const int cg = ttid & 3;        // col group: local cols cg*6 .. cg*6+5

    // stage Wh columns for this block's 8 units (z, r, hh triples), duplicated
    for (int idx = tid; idx < 1024 * 24; idx += SCAN_THREADS) {
        int k = idx / 24, j = idx - k * 24;
        int col = (j >> 3) * U_ + u0 + (j & 7);
        whs2[idx] = pack2(Wh[(size_t)k * N3_ + col], Wh[(size_t)k * N3_ + col]);
    }
    if (tid < 24) bhs[tid] = bh[(tid >> 3) * U_ + u0 + (tid & 7)];
    __syncthreads();

    float* hcT = hc + team * 2048;
    float* recT = recs + team * 1536;

    for (int t = 0; t < T_; t++) {
        const int buf = t & 1;
        const float* hsrc = g_hT[buf];
        float* hdst = g_hT[buf ^ 1];

        u64 acc[6];
#pragma unroll
        for (int j = 0; j < 6; j++) acc[j] = 0ull;

        // prefetch team's first chunk (global chunk index = team)
        float4 pf[4];
        {
            const float4* src =
                reinterpret_cast<const float4*>(hsrc + (size_t)(team * 32) * 64);
#pragma unroll
            for (int j = 0; j < 4; j++) pf[j] = __ldcg(src + ttid + j * 128);
        }

        for (int c = 0; c < 16; c++) {
            __syncthreads();   // prev chunk fully consumed
#pragma unroll
            for (int j = 0; j < 4; j++)
                reinterpret_cast<float4*>(hcT)[ttid + j * 128] = pf[j];
            if (c < 15) {
                const float4* src = reinterpret_cast<const float4*>(
                    hsrc + (size_t)((2 * (c + 1) + team) * 32) * 64);
#pragma unroll
                for (int j = 0; j < 4; j++) pf[j] = __ldcg(src + ttid + j * 128);
            }
            __syncthreads();

            const float* hb = hcT + 2 * rp;
            const u64* wb = whs2 + (size_t)((2 * c + team) * 32) * 24 + cg * 6;
#pragma unroll
            for (int kk = 0; kk < 32; kk++) {
                u64 hp = *reinterpret_cast<const u64*>(hb + kk * 64);
                const u64* wr = wb + kk * 24;
                ulonglong2 w01 = *reinterpret_cast<const ulonglong2*>(wr);
                ulonglong2 w23 = *reinterpret_cast<const ulonglong2*>(wr + 2);
                ulonglong2 w45 = *reinterpret_cast<const ulonglong2*>(wr + 4);
                acc[0] = fma2(hp, w01.x, acc[0]);
                acc[1] = fma2(hp, w01.y, acc[1]);
                acc[2] = fma2(hp, w23.x, acc[2]);
                acc[3] = fma2(hp, w23.y, acc[3]);
                acc[4] = fma2(hp, w45.x, acc[4]);
                acc[5] = fma2(hp, w45.y, acc[5]);
            }
        }

        // write per-team partial rec sums
#pragma unroll
        for (int j = 0; j < 6; j++) {
            float lo, hi;
            unpack2(acc[j], lo, hi);
            recT[(cg * 6 + j) * 64 + 2 * rp] = lo;
            recT[(cg * 6 + j) * 64 + 2 * rp + 1] = hi;
        }
        __syncthreads();

        // gates: 64 rows x 8 units (combine team partials + bias)
#pragma unroll
        for (int o = tid; o < B_ * UPB; o += SCAN_THREADS) {
            int row = o >> 3, uu = o & 7;
            const float* xp = &g_xproj[((size_t)row * T_ + t) * N3_ + u0 + uu];
            float rz = recs[uu * 64 + row] + recs[1536 + uu * 64 + row] + bhs[uu];
            float rr = recs[(8 + uu) * 64 + row] + recs[1536 + (8 + uu) * 64 + row]
                       + bhs[8 + uu];
            float rh = recs[(16 + uu) * 64 + row] + recs[1536 + (16 + uu) * 64 + row]
                       + bhs[16 + uu];
            float xz = xp[0], xr = xp[U_], xh = xp[2 * U_];
            float z = 1.f / (1.f + __expf(-(xz + rz)));
            float r = 1.f / (1.f + __expf(-(xr + rr)));
            float ca = xh + r * rh;
            float cand = 1.f - 2.f / (__expf(2.f * ca) + 1.f);
            int hidx = (u0 + uu) * B_ + row;
            float hold = __ldcg(&hsrc[hidx]);
            float hnew = z * hold + (1.f - z) * cand;
            __stcg(&hdst[hidx], hnew);
            out[((size_t)row * T_ + t) * U_ + u0 + uu] = hnew;
            if (t == T_ - 1)
                out[(size_t)B_ * T_ * U_ + (size_t)row * U_ + u0 + uu] = hnew;
        }

        // grid barrier (monotonic counter, all 128 blocks resident)
        __threadfence();
        __syncthreads();
        if (tid == 0) {
            atomicAdd(&g_bar, 1u);
            unsigned target = (unsigned)(NBLK * (t + 1));
            while (*((volatile unsigned*)&g_bar) < target) { }
        }
        __syncthreads();
    }
}

// ----------------- launch ---------------------------------------------------
extern "C" void kernel_launch(void* const* d_in, const int* in_sizes, int n_in,
                              void* d_out, int out_size) {
    const int* tokens = (const int*)d_in[0];
    const float* hidden = (const float*)d_in[1];
    const float* emb = (const float*)d_in[2];
    const float* Wx = (const float*)d_in[3];
    const float* bx = (const float*)d_in[4];
    const float* Wh = (const float*)d_in[5];
    const float* bh = (const float*)d_in[6];
    float* out = (float*)d_out;
    (void)in_sizes; (void)n_in; (void)out_size;

    cudaFuncSetAttribute(k_scan, cudaFuncAttributeMaxDynamicSharedMemorySize,
                         SCAN_SMEM);

    k_init<<<(B_ * U_ + 255) / 256, 256>>>(hidden);
    dim3 gx(N3_ / 128, (B_ * T_) / 128);
    k_xproj<<<gx, 256>>>(tokens, emb, Wx, bx);
    k_scan<<<NBLK, SCAN_THREADS, SCAN_SMEM>>>(Wh, bh, out);
}

// round 6
// speedup vs baseline: 1.7542x; 1.7542x over previous
#include <cuda_runtime.h>
#include <cuda_bf16.h>
#include <cstdint>

// Problem constants
#define B_  64
#define T_  256
#define E_  512
#define U_  1024
#define N3_ 3072

#define NBLK 128          // scan grid (1 block/SM, all resident -> barrier safe)
#define UPB  8            // GRU units per scan block
#define SCTH 256          // 8 warps: 4 m-tiles x 2 k-teams

// ---- scan smem layout (bytes) ----
// Wsm: [2 planes][24 n][1032 halves]  (stride 2064B, conflict-free ldmatrix)
#define WPLANE 49536
#define OFF_W    0
// hsm: [2 buf][2 planes][64 rows][72 halves] (stride 144B)
#define HPLANE 9216
#define OFF_H    99072
// recs: [2 teams][24 n][68 floats]
#define RECT 6528
#define OFF_RECS 135936
#define OFF_BHS  148992
#define SCAN_SMEM 149120

typedef unsigned long long u64;

// ----------------- device scratch (no allocations allowed) -----------------
__device__ float g_xproj[(size_t)B_ * T_ * N3_];          // [B*T][3U] incl. bx
__device__ __nv_bfloat16 g_hbf[2][2][B_ * U_];            // [buf][hi/lo][row*U+u]
__device__ unsigned g_bar;

// ----------------- ptx helpers ---------------------------------------------
__device__ __forceinline__ uint32_t smem_u32(const void* p) {
    uint32_t a;
    asm("{ .reg .u64 t; cvta.to.shared.u64 t, %1; cvt.u32.u64 %0, t; }"
        : "=r"(a) : "l"(p));
    return a;
}
__device__ __forceinline__ void ldsm_x4(uint32_t* r, uint32_t addr) {
    asm volatile("ldmatrix.sync.aligned.m8n8.x4.shared.b16 {%0,%1,%2,%3}, [%4];"
                 : "=r"(r[0]), "=r"(r[1]), "=r"(r[2]), "=r"(r[3]) : "r"(addr));
}
__device__ __forceinline__ void mma_bf16(float* d, const uint32_t* a,
                                         const uint32_t* b) {
    asm volatile(
        "mma.sync.aligned.m16n8k16.row.col.f32.bf16.bf16.f32 "
        "{%0,%1,%2,%3}, {%4,%5,%6,%7}, {%8,%9}, {%0,%1,%2,%3};"
        : "+f"(d[0]), "+f"(d[1]), "+f"(d[2]), "+f"(d[3])
        : "r"(a[0]), "r"(a[1]), "r"(a[2]), "r"(a[3]), "r"(b[0]), "r"(b[1]));
}

// ----------------- f32x2 helpers (xproj kernel) -----------------------------
__device__ __forceinline__ u64 pack2(float lo, float hi) {
    u64 r;
    asm("mov.b64 %0, {%1, %2};" : "=l"(r)
        : "r"(__float_as_uint(lo)), "r"(__float_as_uint(hi)));
    return r;
}
__device__ __forceinline__ void unpack2(u64 v, float& lo, float& hi) {
    unsigned a, b;
    asm("mov.b64 {%0, %1}, %2;" : "=r"(a), "=r"(b) : "l"(v));
    lo = __uint_as_float(a);
    hi = __uint_as_float(b);
}
__device__ __forceinline__ u64 fma2(u64 a, u64 b, u64 c) {
    u64 d;
    asm("fma.rn.f32x2 %0, %1, %2, %3;" : "=l"(d) : "l"(a), "l"(b), "l"(c));
    return d;
}

// ----------------- init: reset barrier + split h0 into bf16 hi/lo ----------
__global__ void k_init(const float* __restrict__ hidden) {
    int idx = blockIdx.x * blockDim.x + threadIdx.x;
    if (idx == 0) g_bar = 0u;
    if (idx < B_ * U_) {
        float h = hidden[idx];
        __nv_bfloat16 hi = __float2bfloat16(h);
        __nv_bfloat16 lo = __float2bfloat16(h - __bfloat162float(hi));
        g_hbf[0][0][idx] = hi;
        g_hbf[0][1][idx] = lo;
    }
}

// ----------------- kernel 1: x_proj = emb[tokens] @ Wx + bx ----------------
__global__ __launch_bounds__(256, 2)
void k_xproj(const int* __restrict__ tokens, const float* __restrict__ emb,
             const float* __restrict__ Wx, const float* __restrict__ bx) {
    __shared__ float As[16][132];
    __shared__ float Bs[16][132];
    __shared__ int toks[128];

    const int tid = threadIdx.x;
    const int n0 = blockIdx.x * 128;
    const int m0 = blockIdx.y * 128;

    if (tid < 128) toks[tid] = tokens[m0 + tid];

    const int tx = tid & 15;
    const int ty = tid >> 4;

    u64 acc[4][8];
#pragma unroll
    for (int g = 0; g < 4; g++)
#pragma unroll
        for (int j = 0; j < 8; j++) acc[g][j] = 0ull;

    for (int k0 = 0; k0 < E_; k0 += 16) {
        __syncthreads();
#pragma unroll
        for (int q0 = 0; q0 < 2; q0++) {
            int q = tid + q0 * 256;
            int row = q >> 2;
            int kb = (q & 3) << 2;
            const float4 av = *reinterpret_cast<const float4*>(
                &emb[(size_t)toks[row] * E_ + k0 + kb]);
            As[kb + 0][row] = av.x;
            As[kb + 1][row] = av.y;
            As[kb + 2][row] = av.z;
            As[kb + 3][row] = av.w;
        }
#pragma unroll
        for (int q0 = 0; q0 < 2; q0++) {
            int q = tid + q0 * 256;
            int kr = q >> 5;
            int nb = (q & 31) << 2;
            *reinterpret_cast<float4*>(&Bs[kr][nb]) =
                *reinterpret_cast<const float4*>(
                    &Wx[(size_t)(k0 + kr) * N3_ + n0 + nb]);
        }
        __syncthreads();

#pragma unroll
        for (int k = 0; k < 16; k++) {
            ulonglong2 a0 = *reinterpret_cast<const ulonglong2*>(&As[k][ty * 4]);
            ulonglong2 a1 = *reinterpret_cast<const ulonglong2*>(&As[k][64 + ty * 4]);
            float4 b0 = *reinterpret_cast<const float4*>(&Bs[k][tx * 4]);
            float4 b1 = *reinterpret_cast<const float4*>(&Bs[k][64 + tx * 4]);
            u64 ap[4] = {a0.x, a0.y, a1.x, a1.y};
            float bc[8] = {b0.x, b0.y, b0.z, b0.w, b1.x, b1.y, b1.z, b1.w};
#pragma unroll
            for (int j = 0; j < 8; j++) {
                u64 bp = pack2(bc[j], bc[j]);
#pragma unroll
                for (int g = 0; g < 4; g++) acc[g][j] = fma2(ap[g], bp, acc[g][j]);
            }
        }
    }

    float bxv[8];
#pragma unroll
    for (int j = 0; j < 8; j++)
        bxv[j] = bx[n0 + ((j >> 2) ? 64 : 0) + tx * 4 + (j & 3)];

#pragma unroll
    for (int g = 0; g < 4; g++) {
        int r0 = ((g >> 1) << 6) + ty * 4 + ((g & 1) << 1);
        float lo[8], hi[8];
#pragma unroll
        for (int j = 0; j < 8; j++) unpack2(acc[g][j], lo[j], hi[j]);
        float* p0 = &g_xproj[(size_t)(m0 + r0) * N3_ + n0];
        float* p1 = p0 + N3_;
        float4 v;
        v.x = lo[0] + bxv[0]; v.y = lo[1] + bxv[1];
        v.z = lo[2] + bxv[2]; v.w = lo[3] + bxv[3];
        *reinterpret_cast<float4*>(p0 + tx * 4) = v;
        v.x = lo[4] + bxv[4]; v.y = lo[5] + bxv[5];
        v.z = lo[6] + bxv[6]; v.w = lo[7] + bxv[7];
        *reinterpret_cast<float4*>(p0 + 64 + tx * 4) = v;
        v.x = hi[0] + bxv[0]; v.y = hi[1] + bxv[1];
        v.z = hi[2] + bxv[2]; v.w = hi[3] + bxv[3];
        *reinterpret_cast<float4*>(p1 + tx * 4) = v;
        v.x = hi[4] + bxv[4]; v.y = hi[5] + bxv[5];
        v.z = hi[6] + bxv[6]; v.w = hi[7] + bxv[7];
        *reinterpret_cast<float4*>(p1 + 64 + tx * 4) = v;
    }
}

// ----------------- kernel 2: persistent mma.sync GRU scan ------------------
// Block b owns units [8b,8b+8): rec = h @ WhT, M=64 x N=24 x K=1024,
// split-bf16 3-product via mma.sync.m16n8k16. 8 warps = 4 m-tiles x 2 k-teams.
__global__ __launch_bounds__(SCTH, 1)
void k_scan(const float* __restrict__ Wh, const float* __restrict__ bh,
            const float* __restrict__ hidden, float* __restrict__ out) {
    extern __shared__ __align__(128) char smem[];
    const uint32_t sb = smem_u32(smem);
    const int tid = threadIdx.x;
    const int wid = tid >> 5;
    const int lane = tid & 31;
    const int u0 = blockIdx.x * UPB;

    // ---- stage Wh columns as split-bf16 hi/lo ----
    for (int idx = tid; idx < 24 * 1024; idx += SCTH) {
        int n = idx >> 10, k = idx & 1023;
        int col = (n >> 3) * U_ + u0 + (n & 7);
        float w = Wh[(size_t)k * N3_ + col];
        __nv_bfloat16 whi = __float2bfloat16(w);
        __nv_bfloat16 wlo = __float2bfloat16(w - __bfloat162float(whi));
        int off = n * 2064 + k * 2;
        *reinterpret_cast<__nv_bfloat16*>(smem + OFF_W + off) = whi;
        *reinterpret_cast<__nv_bfloat16*>(smem + OFF_W + WPLANE + off) = wlo;
    }
    float* recs = reinterpret_cast<float*>(smem + OFF_RECS);
    float* bhs = reinterpret_cast<float*>(smem + OFF_BHS);
    if (tid < 24) bhs[tid] = bh[(tid >> 3) * U_ + u0 + (tid & 7)];

    // ---- warp geometry ----
    const int m0 = (wid & 3) * 16;   // m-tile rows
    const int tm = wid >> 2;         // k-team
    const int koff = tm * 32;        // k offset within 64-chunk

    // ldmatrix lane offsets (bytes within plane)
    const uint32_t a_off = (uint32_t)((m0 + (lane & 15)) * 144 +
                                      (koff + ((lane >> 4) << 3)) * 2);
    uint32_t b_off[3];
#pragma unroll
    for (int nt = 0; nt < 3; nt++)
        b_off[nt] = (uint32_t)((nt * 8 + (lane & 7)) * 2064 +
                               (koff + ((lane >> 3) << 3)) * 2);

    // h chunk loader mapping: 64 rows x 64 k halves per plane
    const int lrow = tid >> 2;
    const int lkq = (tid & 3) << 4;
    const uint32_t h_st = (uint32_t)(lrow * 144 + lkq * 2);

    // gate mapping: thread -> (row, 2 consecutive units)
    const int grow = tid >> 2;
    const int gup = (tid & 3) << 1;

    float hprev[2];
    {
        const float2 h2 = *reinterpret_cast<const float2*>(
            &hidden[(size_t)grow * U_ + u0 + gup]);
        hprev[0] = h2.x;
        hprev[1] = h2.y;
    }
    __syncthreads();

    for (int t = 0; t < T_; t++) {
        const int buf = t & 1;
        const __nv_bfloat16* hhi = g_hbf[buf][0];
        const __nv_bfloat16* hlo = g_hbf[buf][1];

        float acc[3][4];
#pragma unroll
        for (int nt = 0; nt < 3; nt++)
#pragma unroll
            for (int j = 0; j < 4; j++) acc[nt][j] = 0.f;

        // prefetch chunk 0
        uint4 pf[4];
        {
            const uint4* s0 = reinterpret_cast<const uint4*>(hhi + lrow * U_ + lkq);
            const uint4* s1 = reinterpret_cast<const uint4*>(hlo + lrow * U_ + lkq);
            pf[0] = __ldcg(s0); pf[1] = __ldcg(s0 + 1);
            pf[2] = __ldcg(s1); pf[3] = __ldcg(s1 + 1);
        }

        for (int c = 0; c < 16; c++) {
            const int cb = c & 1;
            char* hb0 = smem + OFF_H + (size_t)(cb * 2) * HPLANE;
            *reinterpret_cast<uint4*>(hb0 + h_st) = pf[0];
            *reinterpret_cast<uint4*>(hb0 + h_st + 16) = pf[1];
            *reinterpret_cast<uint4*>(hb0 + HPLANE + h_st) = pf[2];
            *reinterpret_cast<uint4*>(hb0 + HPLANE + h_st + 16) = pf[3];
            if (c < 15) {
                int k0 = (c + 1) * 64 + lkq;
                const uint4* s0 =
                    reinterpret_cast<const uint4*>(hhi + lrow * U_ + k0);
                const uint4* s1 =
                    reinterpret_cast<const uint4*>(hlo + lrow * U_ + k0);
                pf[0] = __ldcg(s0); pf[1] = __ldcg(s0 + 1);
                pf[2] = __ldcg(s1); pf[3] = __ldcg(s1 + 1);
            }
            __syncthreads();

            // B fragments: 3 n-tiles x (hi,lo), each x4 covers this team's 32 k
            const uint32_t bbase = sb + OFF_W + (uint32_t)c * 128;
            uint32_t bhf[3][4], blf[3][4];
#pragma unroll
            for (int nt = 0; nt < 3; nt++) {
                ldsm_x4(bhf[nt], bbase + b_off[nt]);
                ldsm_x4(blf[nt], bbase + WPLANE + b_off[nt]);
            }
            const uint32_t abase = sb + OFF_H + (uint32_t)(cb * 2) * HPLANE + a_off;
#pragma unroll
            for (int ks = 0; ks < 2; ks++) {
                uint32_t ah[4], al[4];
                ldsm_x4(ah, abase + ks * 32);
                ldsm_x4(al, abase + HPLANE + ks * 32);
#pragma unroll
                for (int nt = 0; nt < 3; nt++) {
                    mma_bf16(acc[nt], ah, &bhf[nt][ks * 2]);
                    mma_bf16(acc[nt], al, &bhf[nt][ks * 2]);
                    mma_bf16(acc[nt], ah, &blf[nt][ks * 2]);
                }
            }
        }

        // write team-partial rec sums: D frag -> recs[tm][n][row]
        {
            float* recT = recs + tm * (RECT / 4);
            int n = 2 * (lane & 3);
            int row = m0 + (lane >> 2);
#pragma unroll
            for (int nt = 0; nt < 3; nt++) {
                int nb_ = nt * 8 + n;
                recT[nb_ * 68 + row] = acc[nt][0];
                recT[(nb_ + 1) * 68 + row] = acc[nt][1];
                recT[nb_ * 68 + row + 8] = acc[nt][2];
                recT[(nb_ + 1) * 68 + row + 8] = acc[nt][3];
            }
        }
        __syncthreads();

        // gates: each thread does (grow, units gup, gup+1)
        const int nbuf = buf ^ 1;
        __nv_bfloat16* dhi = g_hbf[nbuf][0];
        __nv_bfloat16* dlo = g_hbf[nbuf][1];
        {
            const float* xp =
                &g_xproj[((size_t)grow * T_ + t) * N3_ + u0 + gup];
            float2 xz2 = *reinterpret_cast<const float2*>(xp);
            float2 xr2 = *reinterpret_cast<const float2*>(xp + U_);
            float2 xh2 = *reinterpret_cast<const float2*>(xp + 2 * U_);
            float hn[2];
#pragma unroll
            for (int j = 0; j < 2; j++) {
                int uu = gup + j;
                float rz = recs[uu * 68 + grow] +
                           recs[RECT / 4 + uu * 68 + grow] + bhs[uu];
                float rr = recs[(8 + uu) * 68 + grow] +
                           recs[RECT / 4 + (8 + uu) * 68 + grow] + bhs[8 + uu];
                float rh = recs[(16 + uu) * 68 + grow] +
                           recs[RECT / 4 + (16 + uu) * 68 + grow] + bhs[16 + uu];
                float xz = j ? xz2.y : xz2.x;
                float xr = j ? xr2.y : xr2.x;
                float xh = j ? xh2.y : xh2.x;
                float z = 1.f / (1.f + __expf(-(xz + rz)));
                float r = 1.f / (1.f + __expf(-(xr + rr)));
                float ca = xh + r * rh;
                float cand = 1.f - 2.f / (__expf(2.f * ca) + 1.f);
                hn[j] = z * hprev[j] + (1.f - z) * cand;
                hprev[j] = hn[j];
            }
            // store split-bf16 h (2 units packed per 4B)
            __nv_bfloat16 h0 = __float2bfloat16(hn[0]);
            __nv_bfloat16 h1 = __float2bfloat16(hn[1]);
            __nv_bfloat16 l0 = __float2bfloat16(hn[0] - __bfloat162float(h0));
            __nv_bfloat16 l1 = __float2bfloat16(hn[1] - __bfloat162float(h1));
            unsigned phi = ((unsigned)__bfloat16_as_ushort(h1) << 16) |
                           __bfloat16_as_ushort(h0);
            unsigned plo = ((unsigned)__bfloat16_as_ushort(l1) << 16) |
                           __bfloat16_as_ushort(l0);
            int hidx = grow * U_ + u0 + gup;
            __stcg(reinterpret_cast<unsigned*>(&dhi[hidx]), phi);
            __stcg(reinterpret_cast<unsigned*>(&dlo[hidx]), plo);
            float2 o2 = make_float2(hn[0], hn[1]);
            *reinterpret_cast<float2*>(
                &out[((size_t)grow * T_ + t) * U_ + u0 + gup]) = o2;
            if (t == T_ - 1)
                *reinterpret_cast<float2*>(
                    &out[(size_t)B_ * T_ * U_ + (size_t)grow * U_ + u0 + gup]) = o2;
        }

        // grid barrier (monotonic counter, all 128 blocks resident)
        __threadfence();
        __syncthreads();
        if (tid == 0) {
            atomicAdd(&g_bar, 1u);
            unsigned target = (unsigned)(NBLK * (t + 1));
            while (*((volatile unsigned*)&g_bar) < target) { }
        }
        __syncthreads();
    }
}

// ----------------- launch ---------------------------------------------------
extern "C" void kernel_launch(void* const* d_in, const int* in_sizes, int n_in,
                              void* d_out, int out_size) {
    const int* tokens = (const int*)d_in[0];
    const float* hidden = (const float*)d_in[1];
    const float* emb = (const float*)d_in[2];
    const float* Wx = (const float*)d_in[3];
    const float* bx = (const float*)d_in[4];
    const float* Wh = (const float*)d_in[5];
    const float* bh = (const float*)d_in[6];
    float* out = (float*)d_out;
    (void)in_sizes; (void)n_in; (void)out_size;

    cudaFuncSetAttribute(k_scan, cudaFuncAttributeMaxDynamicSharedMemorySize,
                         SCAN_SMEM);

    k_init<<<(B_ * U_ + 255) / 256, 256>>>(hidden);
    dim3 gx(N3_ / 128, (B_ * T_) / 128);
    k_xproj<<<gx, 256>>>(tokens, emb, Wx, bx);
    k_scan<<<NBLK, SCTH, SCAN_SMEM>>>(Wh, bh, hidden, out);
}

// round 8
// speedup vs baseline: 2.2937x; 1.3075x over previous
#include <cuda_runtime.h>
#include <cuda_bf16.h>
#include <cstdint>

// Problem constants
#define B_  64
#define T_  256
#define E_  512
#define U_  1024
#define N3_ 3072

#define NBLK 128          // scan grid (1 block/SM, all resident -> barrier safe)
#define UPB  8            // GRU units per scan block
#define SCTH 256          // 8 warps: 4 m-tiles x 2 k-teams

// ---- scan smem layout (bytes) ----
#define WPLANE 49536                 // [24 n][1032 halves] stride 2064B
#define OFF_W    0
#define HPLANE 17408                 // [64 rows][136 halves] stride 272B
#define OFF_H    99072               // [2 buf][2 plane][HPLANE]
#define OFF_RECS 168704              // [2 teams][24 n][68 floats]
#define RECF     1632                // floats per team
#define OFF_BHS  181760
#define SCAN_SMEM 181888

// ---- xproj smem layout (bytes) ----
#define XP_TOK  0                    // 128 ints
#define XP_A    512                  // [3 stages][2 planes][128 rows * 48B]
#define XP_APLANE 6144
#define XP_B    37376                // [3 stages][2 planes][64 rows * 48B]
#define XP_BPLANE 3072
#define XP_SMEM 55808

typedef unsigned long long u64;

// ----------------- device scratch (no allocations allowed) -----------------
__device__ float g_xproj[(size_t)B_ * T_ * N3_];          // [B*T][3U] incl. bx
__device__ __nv_bfloat16 g_hbf[2][2][B_ * U_];            // [buf][hi/lo][row*U+u]
__device__ __nv_bfloat16 g_embh[(size_t)32000 * E_];      // [tok][k]
__device__ __nv_bfloat16 g_embl[(size_t)32000 * E_];
__device__ __nv_bfloat16 g_wxh[(size_t)N3_ * E_];         // TRANSPOSED [n][k]
__device__ __nv_bfloat16 g_wxl[(size_t)N3_ * E_];
__device__ unsigned g_bar;

// ----------------- ptx helpers ---------------------------------------------
__device__ __forceinline__ uint32_t smem_u32(const void* p) {
    uint32_t a;
    asm("{ .reg .u64 t; cvta.to.shared.u64 t, %1; cvt.u32.u64 %0, t; }"
        : "=r"(a) : "l"(p));
    return a;
}
__device__ __forceinline__ void ldsm_x4(uint32_t* r, uint32_t addr) {
    asm volatile("ldmatrix.sync.aligned.m8n8.x4.shared.b16 {%0,%1,%2,%3}, [%4];"
                 : "=r"(r[0]), "=r"(r[1]), "=r"(r[2]), "=r"(r[3]) : "r"(addr));
}
__device__ __forceinline__ void mma_bf16(float* d, const uint32_t* a,
                                         const uint32_t* b) {
    asm volatile(
        "mma.sync.aligned.m16n8k16.row.col.f32.bf16.bf16.f32 "
        "{%0,%1,%2,%3}, {%4,%5,%6,%7}, {%8,%9}, {%0,%1,%2,%3};"
        : "+f"(d[0]), "+f"(d[1]), "+f"(d[2]), "+f"(d[3])
        : "r"(a[0]), "r"(a[1]), "r"(a[2]), "r"(a[3]), "r"(b[0]), "r"(b[1]));
}
__device__ __forceinline__ void cpa16(uint32_t dst, const void* src) {
    asm volatile("cp.async.cg.shared.global [%0], [%1], 16;"
                 :: "r"(dst), "l"(src) : "memory");
}
__device__ __forceinline__ void cpa_commit() {
    asm volatile("cp.async.commit_group;" ::: "memory");
}
template <int N>
__device__ __forceinline__ void cpa_wait() {
    asm volatile("cp.async.wait_group %0;" :: "n"(N) : "memory");
}

// ----------------- init: reset barrier + split h0 into bf16 hi/lo ----------
__global__ void k_init(const float* __restrict__ hidden) {
    int idx = blockIdx.x * blockDim.x + threadIdx.x;
    if (idx == 0) g_bar = 0u;
    if (idx < B_ * U_) {
        float h = hidden[idx];
        __nv_bfloat16 hi = __float2bfloat16(h);
        __nv_bfloat16 lo = __float2bfloat16(h - __bfloat162float(hi));
        g_hbf[0][0][idx] = hi;
        g_hbf[0][1][idx] = lo;
    }
}

// ----------------- prep: split emb (as-is) and Wx (TRANSPOSED) -------------
__global__ void k_prep(const float* __restrict__ emb,
                       const float* __restrict__ Wx) {
    const size_t n1 = (size_t)32000 * E_;
    const size_t n2 = (size_t)N3_ * E_;
    for (size_t i = (size_t)blockIdx.x * blockDim.x + threadIdx.x; i < n1 + n2;
         i += (size_t)gridDim.x * blockDim.x) {
        if (i < n1) {
            float v = emb[i];
            __nv_bfloat16 hi = __float2bfloat16(v);
            g_embh[i] = hi;
            g_embl[i] = __float2bfloat16(v - __bfloat162float(hi));
        } else {
            size_t j = i - n1;          // j = n * E + k  (transposed layout)
            int n = (int)(j >> 9);      // / E_
            int k = (int)(j & (E_ - 1));
            float v = Wx[(size_t)k * N3_ + n];
            __nv_bfloat16 hi = __float2bfloat16(v);
            g_wxh[j] = hi;
            g_wxl[j] = __float2bfloat16(v - __bfloat162float(hi));
        }
    }
}

// ----------------- kernel 1: tensor-core x_proj ----------------------------
// x_proj = emb[tokens] @ Wx + bx, split-bf16 3-product mma.sync.
// Tile 128m x 64n, K=512 in 32 k16 steps, cp.async 3-stage pipeline.
// B staged from pre-transposed [n][k] planes; NON-trans ldmatrix (proven path).
__global__ __launch_bounds__(256, 2)
void k_xproj_tc(const int* __restrict__ tokens, const float* __restrict__ bx) {
    extern __shared__ char xs[];
    const uint32_t sb = smem_u32(xs);
    const int tid = threadIdx.x;
    const int wid = tid >> 5;
    const int lane = tid & 31;
    const int n0 = blockIdx.x * 64;
    const int m0 = blockIdx.y * 128;

    int* toks = reinterpret_cast<int*>(xs + XP_TOK);
    if (tid < 128) toks[tid] = tokens[m0 + tid];
    __syncthreads();

    // A loader: 128 rows x 2 segs (8 halves each), both planes per thread
    const int arow = tid >> 1, aseg = tid & 1;
    const size_t aoff = (size_t)toks[arow] * E_ + aseg * 8;
    const uint32_t adst = sb + XP_A + arow * 48 + aseg * 16;
    // B loader: 64 n-rows x 2 segs x 2 planes, one cp per thread
    const int bplane = tid >> 7, b2 = tid & 127;
    const int brow = b2 >> 1, bseg = b2 & 1;
    const __nv_bfloat16* wsrc =
        (bplane ? g_wxl : g_wxh) + (size_t)(n0 + brow) * E_ + bseg * 8;
    const uint32_t bdst =
        sb + XP_B + bplane * XP_BPLANE + brow * 48 + bseg * 16;

#define XP_ISSUE(s, buf)                                               \
    {                                                                  \
        int k0_ = (s) * 16;                                            \
        cpa16(adst + (buf) * 12288, g_embh + aoff + k0_);              \
        cpa16(adst + (buf) * 12288 + XP_APLANE, g_embl + aoff + k0_);  \
        cpa16(bdst + (buf) * 6144, wsrc + k0_);                        \
        cpa_commit();                                                  \
    }

    const int mw = wid & 3, nw = wid >> 2;
    float acc[2][4][4];
#pragma unroll
    for (int mt = 0; mt < 2; mt++)
#pragma unroll
        for (int nt = 0; nt < 4; nt++)
#pragma unroll
            for (int j = 0; j < 4; j++) acc[mt][nt][j] = 0.f;

    const uint32_t a_off =
        (uint32_t)((mw * 32 + (lane & 15)) * 48 + ((lane >> 4) << 3) * 2);
    // non-trans B from [n][k]: lanes 0-7 n+0-7/k0-7, 8-15 n+0-7/k8-15,
    // 16-23 n+8-15/k0-7, 24-31 n+8-15/k8-15
    const uint32_t b_off =
        (uint32_t)((nw * 32 + (lane & 7) + ((lane >> 4) << 3)) * 48 +
                   (((lane >> 3) & 1) << 4));

    XP_ISSUE(0, 0);
    XP_ISSUE(1, 1);

    for (int s = 0; s < 32; s++) {
        const int buf = s % 3;
        cpa_wait<1>();
        __syncthreads();

        const uint32_t ab = sb + XP_A + buf * 12288 + a_off;
        const uint32_t bb = sb + XP_B + buf * 6144 + b_off;
        uint32_t ah[2][4], al[2][4], bhf[2][4], blf[2][4];
        ldsm_x4(ah[0], ab);
        ldsm_x4(ah[1], ab + 16 * 48);
        ldsm_x4(al[0], ab + XP_APLANE);
        ldsm_x4(al[1], ab + XP_APLANE + 16 * 48);
        ldsm_x4(bhf[0], bb);
        ldsm_x4(bhf[1], bb + 16 * 48);
        ldsm_x4(blf[0], bb + XP_BPLANE);
        ldsm_x4(blf[1], bb + XP_BPLANE + 16 * 48);

#pragma unroll
        for (int mt = 0; mt < 2; mt++)
#pragma unroll
            for (int nt = 0; nt < 4; nt++) {
                const uint32_t* fh = &bhf[nt >> 1][(nt & 1) * 2];
                const uint32_t* fl = &blf[nt >> 1][(nt & 1) * 2];
                mma_bf16(acc[mt][nt], ah[mt], fh);
                mma_bf16(acc[mt][nt], al[mt], fh);
                mma_bf16(acc[mt][nt], ah[mt], fl);
            }

        if (s + 2 < 32) XP_ISSUE(s + 2, (s + 2) % 3);
    }

    // epilogue: add bias, store f32
    const int r0 = m0 + mw * 32 + (lane >> 2);
    const int c0 = n0 + nw * 32 + (lane & 3) * 2;
#pragma unroll
    for (int mt = 0; mt < 2; mt++)
#pragma unroll
        for (int nt = 0; nt < 4; nt++) {
            int rr = r0 + mt * 16, cc = c0 + nt * 8;
            float b0 = bx[cc], b1 = bx[cc + 1];
            float2 v0 = make_float2(acc[mt][nt][0] + b0, acc[mt][nt][1] + b1);
            float2 v1 = make_float2(acc[mt][nt][2] + b0, acc[mt][nt][3] + b1);
            *reinterpret_cast<float2*>(&g_xproj[(size_t)rr * N3_ + cc]) = v0;
            *reinterpret_cast<float2*>(&g_xproj[(size_t)(rr + 8) * N3_ + cc]) = v1;
        }
#undef XP_ISSUE
}

// ----------------- kernel 2: persistent mma.sync GRU scan ------------------
// Block b owns units [8b,8b+8): rec = h @ WhT, M=64 x N=24 x K=1024,
// split-bf16 3-product. 8 warps = 4 m-tiles x 2 k-teams. K in 8 chunks of 128.
__global__ __launch_bounds__(SCTH, 1)
void k_scan(const float* __restrict__ Wh, const float* __restrict__ bh,
            const float* __restrict__ hidden, float* __restrict__ out) {
    extern __shared__ __align__(128) char smem[];
    const uint32_t sb = smem_u32(smem);
    const int tid = threadIdx.x;
    const int wid = tid >> 5;
    const int lane = tid & 31;
    const int u0 = blockIdx.x * UPB;

    // ---- stage Wh columns as split-bf16 hi/lo ----
    for (int idx = tid; idx < 24 * 1024; idx += SCTH) {
        int n = idx >> 10, k = idx & 1023;
        int col = (n >> 3) * U_ + u0 + (n & 7);
        float w = Wh[(size_t)k * N3_ + col];
        __nv_bfloat16 whi = __float2bfloat16(w);
        __nv_bfloat16 wlo = __float2bfloat16(w - __bfloat162float(whi));
        int off = n * 2064 + k * 2;
        *reinterpret_cast<__nv_bfloat16*>(smem + OFF_W + off) = whi;
        *reinterpret_cast<__nv_bfloat16*>(smem + OFF_W + WPLANE + off) = wlo;
    }
    float* recs = reinterpret_cast<float*>(smem + OFF_RECS);
    float* bhs = reinterpret_cast<float*>(smem + OFF_BHS);
    if (tid < 24) bhs[tid] = bh[(tid >> 3) * U_ + u0 + (tid & 7)];

    // ---- warp geometry ----
    const int m0 = (wid & 3) * 16;   // m-tile rows
    const int tm = wid >> 2;         // k-team
    const int koff = tm * 64;        // team k offset within 128-chunk

    const uint32_t a_off = (uint32_t)((m0 + (lane & 15)) * 272 +
                                      ((lane >> 4) << 3) * 2);
    uint32_t b_off[3];
#pragma unroll
    for (int nt = 0; nt < 3; nt++)
        b_off[nt] = (uint32_t)((nt * 8 + (lane & 7)) * 2064 +
                               (((lane >> 3) & 3) << 3) * 2);

    // h chunk loader: per chunk 64 rows x 128 halves per plane
    const int lrow = tid >> 2;
    const int lkq = (tid & 3) << 5;                 // half offset 0/32/64/96
    const uint32_t h_st = (uint32_t)(lrow * 272 + lkq * 2);

    // gate mapping
    const int grow = tid >> 2;
    const int gup = (tid & 3) << 1;

    float hprev[2];
    {
        const float2 h2 = *reinterpret_cast<const float2*>(
            &hidden[(size_t)grow * U_ + u0 + gup]);
        hprev[0] = h2.x;
        hprev[1] = h2.y;
    }
    __syncthreads();

    for (int t = 0; t < T_; t++) {
        const int buf = t & 1;
        const __nv_bfloat16* hhi = g_hbf[buf][0];
        const __nv_bfloat16* hlo = g_hbf[buf][1];

        float acc[3][4];
#pragma unroll
        for (int nt = 0; nt < 3; nt++)
#pragma unroll
            for (int j = 0; j < 4; j++) acc[nt][j] = 0.f;

        // prefetch chunk 0 (8 x 16B per thread)
        uint4 pf[8];
        {
            const uint4* s0 = reinterpret_cast<const uint4*>(hhi + lrow * U_ + lkq);
            const uint4* s1 = reinterpret_cast<const uint4*>(hlo + lrow * U_ + lkq);
#pragma unroll
            for (int j = 0; j < 4; j++) { pf[j] = __ldcg(s0 + j); }
#pragma unroll
            for (int j = 0; j < 4; j++) { pf[4 + j] = __ldcg(s1 + j); }
        }

        for (int c = 0; c < 8; c++) {
            const int cb = c & 1;
            char* hb = smem + OFF_H + (size_t)(cb * 2) * HPLANE;
#pragma unroll
            for (int j = 0; j < 4; j++) {
                *reinterpret_cast<uint4*>(hb + h_st + j * 16) = pf[j];
                *reinterpret_cast<uint4*>(hb + HPLANE + h_st + j * 16) = pf[4 + j];
            }
            if (c < 7) {
                int k0 = (c + 1) * 128 + lkq;
                const uint4* s0 =
                    reinterpret_cast<const uint4*>(hhi + lrow * U_ + k0);
                const uint4* s1 =
                    reinterpret_cast<const uint4*>(hlo + lrow * U_ + k0);
#pragma unroll
                for (int j = 0; j < 4; j++) { pf[j] = __ldcg(s0 + j); }
#pragma unroll
                for (int j = 0; j < 4; j++) { pf[4 + j] = __ldcg(s1 + j); }
            }
            __syncthreads();

#pragma unroll
            for (int sub = 0; sub < 2; sub++) {
                const uint32_t kg = (uint32_t)(c * 128 + koff + sub * 32);
                const uint32_t bbase = sb + OFF_W + kg * 2;
                uint32_t bhf[3][4], blf[3][4];
#pragma unroll
                for (int nt = 0; nt < 3; nt++) {
                    ldsm_x4(bhf[nt], bbase + b_off[nt]);
                    ldsm_x4(blf[nt], bbase + WPLANE + b_off[nt]);
                }
                const uint32_t abase = sb + OFF_H + (uint32_t)(cb * 2) * HPLANE +
                                       a_off + (uint32_t)(koff + sub * 32) * 2;
#pragma unroll
                for (int ks = 0; ks < 2; ks++) {
                    uint32_t ah[4], al[4];
                    ldsm_x4(ah, abase + ks * 32);
                    ldsm_x4(al, abase + HPLANE + ks * 32);
#pragma unroll
                    for (int nt = 0; nt < 3; nt++) {
                        mma_bf16(acc[nt], ah, &bhf[nt][ks * 2]);
                        mma_bf16(acc[nt], al, &bhf[nt][ks * 2]);
                        mma_bf16(acc[nt], ah, &blf[nt][ks * 2]);
                    }
                }
            }
        }

        // write team-partial rec sums
        {
            float* recT = recs + tm * RECF;
            int n = 2 * (lane & 3);
            int row = m0 + (lane >> 2);
#pragma unroll
            for (int nt = 0; nt < 3; nt++) {
                int nb_ = nt * 8 + n;
                recT[nb_ * 68 + row] = acc[nt][0];
                recT[(nb_ + 1) * 68 + row] = acc[nt][1];
                recT[nb_ * 68 + row + 8] = acc[nt][2];
                recT[(nb_ + 1) * 68 + row + 8] = acc[nt][3];
            }
        }
        __syncthreads();

        // gates
        const int nbuf = buf ^ 1;
        __nv_bfloat16* dhi = g_hbf[nbuf][0];
        __nv_bfloat16* dlo = g_hbf[nbuf][1];
        {
            const float* xp = &g_xproj[((size_t)grow * T_ + t) * N3_ + u0 + gup];
            float2 xz2 = *reinterpret_cast<const float2*>(xp);
            float2 xr2 = *reinterpret_cast<const float2*>(xp + U_);
            float2 xh2 = *reinterpret_cast<const float2*>(xp + 2 * U_);
            float hn[2];
#pragma unroll
            for (int j = 0; j < 2; j++) {
                int uu = gup + j;
                float rz = recs[uu * 68 + grow] + recs[RECF + uu * 68 + grow] +
                           bhs[uu];
                float rr = recs[(8 + uu) * 68 + grow] +
                           recs[RECF + (8 + uu) * 68 + grow] + bhs[8 + uu];
                float rh = recs[(16 + uu) * 68 + grow] +
                           recs[RECF + (16 + uu) * 68 + grow] + bhs[16 + uu];
                float xz = j ? xz2.y : xz2.x;
                float xr = j ? xr2.y : xr2.x;
                float xh = j ? xh2.y : xh2.x;
                float z = 1.f / (1.f + __expf(-(xz + rz)));
                float r = 1.f / (1.f + __expf(-(xr + rr)));
                float ca = xh + r * rh;
                float cand = 1.f - 2.f / (__expf(2.f * ca) + 1.f);
                hn[j] = z * hprev[j] + (1.f - z) * cand;
                hprev[j] = hn[j];
            }
            __nv_bfloat16 h0 = __float2bfloat16(hn[0]);
            __nv_bfloat16 h1 = __float2bfloat16(hn[1]);
            __nv_bfloat16 l0 = __float2bfloat16(hn[0] - __bfloat162float(h0));
            __nv_bfloat16 l1 = __float2bfloat16(hn[1] - __bfloat162float(h1));
            unsigned phi = ((unsigned)__bfloat16_as_ushort(h1) << 16) |
                           __bfloat16_as_ushort(h0);
            unsigned plo = ((unsigned)__bfloat16_as_ushort(l1) << 16) |
                           __bfloat16_as_ushort(l0);
            int hidx = grow * U_ + u0 + gup;
            __stcg(reinterpret_cast<unsigned*>(&dhi[hidx]), phi);
            __stcg(reinterpret_cast<unsigned*>(&dlo[hidx]), plo);
            float2 o2 = make_float2(hn[0], hn[1]);
            *reinterpret_cast<float2*>(
                &out[((size_t)grow * T_ + t) * U_ + u0 + gup]) = o2;
            if (t == T_ - 1)
                *reinterpret_cast<float2*>(
                    &out[(size_t)B_ * T_ * U_ + (size_t)grow * U_ + u0 + gup]) = o2;
        }

        // grid barrier (monotonic counter, all 128 blocks resident)
        __threadfence();
        __syncthreads();
        if (tid == 0) {
            atomicAdd(&g_bar, 1u);
            unsigned target = (unsigned)(NBLK * (t + 1));
            while (*((volatile unsigned*)&g_bar) < target) { }
        }
        __syncthreads();
    }
}

// ----------------- launch ---------------------------------------------------
extern "C" void kernel_launch(void* const* d_in, const int* in_sizes, int n_in,
                              void* d_out, int out_size) {
    const int* tokens = (const int*)d_in[0];
    const float* hidden = (const float*)d_in[1];
    const float* emb = (const float*)d_in[2];
    const float* Wx = (const float*)d_in[3];
    const float* bx = (const float*)d_in[4];
    const float* Wh = (const float*)d_in[5];
    const float* bh = (const float*)d_in[6];
    float* out = (float*)d_out;
    (void)in_sizes; (void)n_in; (void)out_size;

    cudaFuncSetAttribute(k_scan, cudaFuncAttributeMaxDynamicSharedMemorySize,
                         SCAN_SMEM);
    cudaFuncSetAttribute(k_xproj_tc, cudaFuncAttributeMaxDynamicSharedMemorySize,
                         XP_SMEM);

    k_init<<<(B_ * U_ + 255) / 256, 256>>>(hidden);
    k_prep<<<1024, 256>>>(emb, Wx);
    dim3 gx(N3_ / 64, (B_ * T_) / 128);
    k_xproj_tc<<<gx, 256, XP_SMEM>>>(tokens, bx);
    k_scan<<<NBLK, SCTH, SCAN_SMEM>>>(Wh, bh, hidden, out);
}

// round 11
// speedup vs baseline: 2.4159x; 1.0533x over previous
#include <cuda_runtime.h>
#include <cuda_bf16.h>
#include <cstdint>

// Problem constants
#define B_  64
#define T_  256
#define E_  512
#define U_  1024
#define N3_ 3072

#define NBLK 128          // scan grid (1 block/SM, all resident -> barrier safe)
#define UPB  8            // GRU units per scan block
#define SCTH 256          // 8 warps: 4 k-teams x 2 m-halves

// ---- scan smem layout (bytes) ----
#define WPLANE 49536                 // [24 n][1032 halves] stride 2064B
#define OFF_W    0                   // 2 planes (hi, lo)
#define HPLANE 17408                 // [64 rows][136 halves] stride 272B
#define OFF_H    99072               // [2 buf][2 plane][HPLANE]
#define OFF_RECS 168704              // [4 teams][24 n][68 floats]
#define RECF     1632                // floats per team
#define OFF_BHS  194816
#define SCAN_SMEM 194944

// ---- xproj smem layout (bytes) ----
#define XP_TOK  0                    // 128 ints
#define XP_A    512                  // [3 stages][2 planes][128 rows * 48B]
#define XP_APLANE 6144
#define XP_B    37376                // [3 stages][2 planes][64 rows * 48B]
#define XP_BPLANE 3072
#define XP_SMEM 55808

// ----------------- device scratch (no allocations allowed) -----------------
__device__ float g_xproj[(size_t)B_ * T_ * N3_];          // [B*T][3U] incl. bx
__device__ __nv_bfloat16 g_hbf[2][2][B_ * U_];            // [buf][hi/lo][row*U+u]
__device__ __nv_bfloat16 g_embh[(size_t)32000 * E_];      // [tok][k]
__device__ __nv_bfloat16 g_embl[(size_t)32000 * E_];
__device__ __nv_bfloat16 g_wxh[(size_t)N3_ * E_];         // TRANSPOSED [n][k]
__device__ __nv_bfloat16 g_wxl[(size_t)N3_ * E_];
__device__ unsigned g_bar;

// ----------------- ptx helpers ---------------------------------------------
__device__ __forceinline__ uint32_t smem_u32(const void* p) {
    uint32_t a;
    asm("{ .reg .u64 t; cvta.to.shared.u64 t, %1; cvt.u32.u64 %0, t; }"
        : "=r"(a) : "l"(p));
    return a;
}
__device__ __forceinline__ void ldsm_x4(uint32_t* r, uint32_t addr) {
    asm volatile("ldmatrix.sync.aligned.m8n8.x4.shared.b16 {%0,%1,%2,%3}, [%4];"
                 : "=r"(r[0]), "=r"(r[1]), "=r"(r[2]), "=r"(r[3]) : "r"(addr));
}
__device__ __forceinline__ void mma_bf16(float* d, const uint32_t* a,
                                         const uint32_t* b) {
    asm volatile(
        "mma.sync.aligned.m16n8k16.row.col.f32.bf16.bf16.f32 "
        "{%0,%1,%2,%3}, {%4,%5,%6,%7}, {%8,%9}, {%0,%1,%2,%3};"
        : "+f"(d[0]), "+f"(d[1]), "+f"(d[2]), "+f"(d[3])
        : "r"(a[0]), "r"(a[1]), "r"(a[2]), "r"(a[3]), "r"(b[0]), "r"(b[1]));
}
__device__ __forceinline__ void cpa16(uint32_t dst, const void* src) {
    asm volatile("cp.async.cg.shared.global [%0], [%1], 16;"
                 :: "r"(dst), "l"(src) : "memory");
}
__device__ __forceinline__ void cpa_commit() {
    asm volatile("cp.async.commit_group;" ::: "memory");
}
template <int N>
__device__ __forceinline__ void cpa_wait() {
    asm volatile("cp.async.wait_group %0;" :: "n"(N) : "memory");
}

// ----------------- init: reset barrier + split h0 into bf16 hi/lo ----------
__global__ void k_init(const float* __restrict__ hidden) {
    int idx = blockIdx.x * blockDim.x + threadIdx.x;
    if (idx == 0) g_bar = 0u;
    if (idx < B_ * U_) {
        float h = hidden[idx];
        __nv_bfloat16 hi = __float2bfloat16(h);
        __nv_bfloat16 lo = __float2bfloat16(h - __bfloat162float(hi));
        g_hbf[0][0][idx] = hi;
        g_hbf[0][1][idx] = lo;
    }
}

// ----------------- prep: split emb (as-is) and Wx (TRANSPOSED) -------------
__global__ void k_prep(const float* __restrict__ emb,
                       const float* __restrict__ Wx) {
    const size_t n1 = (size_t)32000 * E_;
    const size_t n2 = (size_t)N3_ * E_;
    for (size_t i = (size_t)blockIdx.x * blockDim.x + threadIdx.x; i < n1 + n2;
         i += (size_t)gridDim.x * blockDim.x) {
        if (i < n1) {
            float v = emb[i];
            __nv_bfloat16 hi = __float2bfloat16(v);
            g_embh[i] = hi;
            g_embl[i] = __float2bfloat16(v - __bfloat162float(hi));
        } else {
            size_t j = i - n1;          // j = n * E + k  (transposed layout)
            int n = (int)(j >> 9);      // / E_
            int k = (int)(j & (E_ - 1));
            float v = Wx[(size_t)k * N3_ + n];
            __nv_bfloat16 hi = __float2bfloat16(v);
            g_wxh[j] = hi;
            g_wxl[j] = __float2bfloat16(v - __bfloat162float(hi));
        }
    }
}

// ----------------- kernel 1: tensor-core x_proj (round-8 proven) -----------
__global__ __launch_bounds__(256, 2)
void k_xproj_tc(const int* __restrict__ tokens, const float* __restrict__ bx) {
    extern __shared__ char xs[];
    const uint32_t sb = smem_u32(xs);
    const int tid = threadIdx.x;
    const int wid = tid >> 5;
    const int lane = tid & 31;
    const int n0 = blockIdx.x * 64;
    const int m0 = blockIdx.y * 128;

    int* toks = reinterpret_cast<int*>(xs + XP_TOK);
    if (tid < 128) toks[tid] = tokens[m0 + tid];
    __syncthreads();

    const int arow = tid >> 1, aseg = tid & 1;
    const size_t aoff = (size_t)toks[arow] * E_ + aseg * 8;
    const uint32_t adst = sb + XP_A + arow * 48 + aseg * 16;
    const int bplane = tid >> 7, b2 = tid & 127;
    const int brow = b2 >> 1, bseg = b2 & 1;
    const __nv_bfloat16* wsrc =
        (bplane ? g_wxl : g_wxh) + (size_t)(n0 + brow) * E_ + bseg * 8;
    const uint32_t bdst =
        sb + XP_B + bplane * XP_BPLANE + brow * 48 + bseg * 16;

#define XP_ISSUE(s, buf)                                               \
    {                                                                  \
        int k0_ = (s) * 16;                                            \
        cpa16(adst + (buf) * 12288, g_embh + aoff + k0_);              \
        cpa16(adst + (buf) * 12288 + XP_APLANE, g_embl + aoff + k0_);  \
        cpa16(bdst + (buf) * 6144, wsrc + k0_);                        \
        cpa_commit();                                                  \
    }

    const int mw = wid & 3, nw = wid >> 2;
    float acc[2][4][4];
#pragma unroll
    for (int mt = 0; mt < 2; mt++)
#pragma unroll
        for (int nt = 0; nt < 4; nt++)
#pragma unroll
            for (int j = 0; j < 4; j++) acc[mt][nt][j] = 0.f;

    const uint32_t a_off =
        (uint32_t)((mw * 32 + (lane & 15)) * 48 + ((lane >> 4) << 3) * 2);
    const uint32_t b_off =
        (uint32_t)((nw * 32 + (lane & 7) + ((lane >> 4) << 3)) * 48 +
                   (((lane >> 3) & 1) << 4));

    XP_ISSUE(0, 0);
    XP_ISSUE(1, 1);

    for (int s = 0; s < 32; s++) {
        const int buf = s % 3;
        cpa_wait<1>();
        __syncthreads();

        const uint32_t ab = sb + XP_A + buf * 12288 + a_off;
        const uint32_t bb = sb + XP_B + buf * 6144 + b_off;
        uint32_t ah[2][4], al[2][4], bhf[2][4], blf[2][4];
        ldsm_x4(ah[0], ab);
        ldsm_x4(ah[1], ab + 16 * 48);
        ldsm_x4(al[0], ab + XP_APLANE);
        ldsm_x4(al[1], ab + XP_APLANE + 16 * 48);
        ldsm_x4(bhf[0], bb);
        ldsm_x4(bhf[1], bb + 16 * 48);
        ldsm_x4(blf[0], bb + XP_BPLANE);
        ldsm_x4(blf[1], bb + XP_BPLANE + 16 * 48);

#pragma unroll
        for (int mt = 0; mt < 2; mt++)
#pragma unroll
            for (int nt = 0; nt < 4; nt++) {
                const uint32_t* fh = &bhf[nt >> 1][(nt & 1) * 2];
                const uint32_t* fl = &blf[nt >> 1][(nt & 1) * 2];
                mma_bf16(acc[mt][nt], ah[mt], fh);
                mma_bf16(acc[mt][nt], al[mt], fh);
                mma_bf16(acc[mt][nt], ah[mt], fl);
            }

        if (s + 2 < 32) XP_ISSUE(s + 2, (s + 2) % 3);
    }

    const int r0 = m0 + mw * 32 + (lane >> 2);
    const int c0 = n0 + nw * 32 + (lane & 3) * 2;
#pragma unroll
    for (int mt = 0; mt < 2; mt++)
#pragma unroll
        for (int nt = 0; nt < 4; nt++) {
            int rr = r0 + mt * 16, cc = c0 + nt * 8;
            float b0 = bx[cc], b1 = bx[cc + 1];
            float2 v0 = make_float2(acc[mt][nt][0] + b0, acc[mt][nt][1] + b1);
            float2 v1 = make_float2(acc[mt][nt][2] + b0, acc[mt][nt][3] + b1);
            *reinterpret_cast<float2*>(&g_xproj[(size_t)rr * N3_ + cc]) = v0;
            *reinterpret_cast<float2*>(&g_xproj[(size_t)(rr + 8) * N3_ + cc]) = v1;
        }
#undef XP_ISSUE
}

// ----------------- kernel 2: persistent mma.sync GRU scan ------------------
// Round-8 numerics (split-bf16 3-product), new geometry: 4 k-teams x 2
// m-halves so B fragments are reused across both m16 tiles. K in 8 chunks
// of 128 (32 k per team per chunk), h double-buffered in smem.
__global__ __launch_bounds__(SCTH, 1)
void k_scan(const float* __restrict__ Wh, const float* __restrict__ bh,
            const float* __restrict__ hidden, float* __restrict__ out) {
    extern __shared__ __align__(128) char smem[];
    const uint32_t sb = smem_u32(smem);
    const int tid = threadIdx.x;
    const int wid = tid >> 5;
    const int lane = tid & 31;
    const int u0 = blockIdx.x * UPB;

    // ---- stage Wh columns as split-bf16 hi/lo ----
    for (int idx = tid; idx < 24 * 1024; idx += SCTH) {
        int n = idx >> 10, k = idx & 1023;
        int col = (n >> 3) * U_ + u0 + (n & 7);
        float w = Wh[(size_t)k * N3_ + col];
        __nv_bfloat16 whi = __float2bfloat16(w);
        __nv_bfloat16 wlo = __float2bfloat16(w - __bfloat162float(whi));
        int off = n * 2064 + k * 2;
        *reinterpret_cast<__nv_bfloat16*>(smem + OFF_W + off) = whi;
        *reinterpret_cast<__nv_bfloat16*>(smem + OFF_W + WPLANE + off) = wlo;
    }
    float* recs = reinterpret_cast<float*>(smem + OFF_RECS);
    float* bhs = reinterpret_cast<float*>(smem + OFF_BHS);
    if (tid < 24) bhs[tid] = bh[(tid >> 3) * U_ + u0 + (tid & 7)];

    // ---- warp geometry: 4 k-teams x 2 m-halves ----
    const int tm = wid & 3;          // k-team: 32 k per 128-chunk
    const int mh = wid >> 2;         // m-half: rows mh*32 .. +31

    const uint32_t a_row_off = (uint32_t)((mh * 32 + (lane & 15)) * 272 +
                                          ((lane >> 4) << 3) * 2);
    uint32_t b_off[3];
#pragma unroll
    for (int nt = 0; nt < 3; nt++)
        b_off[nt] = (uint32_t)((nt * 8 + (lane & 7)) * 2064 +
                               (((lane >> 3) & 3) << 4));

    // h chunk loader: per chunk 64 rows x 128 halves per plane (272B stride)
    const int lrow = tid >> 2;
    const int lkq = (tid & 3) << 5;                 // half offset 0/32/64/96
    const uint32_t h_st = (uint32_t)(lrow * 272 + lkq * 2);

    // gate mapping
    const int grow = tid >> 2;
    const int gup = (tid & 3) << 1;

    float hprev[2];
    {
        const float2 h2 = *reinterpret_cast<const float2*>(
            &hidden[(size_t)grow * U_ + u0 + gup]);
        hprev[0] = h2.x;
        hprev[1] = h2.y;
    }
    __syncthreads();

    for (int t = 0; t < T_; t++) {
        const int buf = t & 1;
        const __nv_bfloat16* hhi = g_hbf[buf][0];
        const __nv_bfloat16* hlo = g_hbf[buf][1];

        float acc[2][3][4];
#pragma unroll
        for (int mt = 0; mt < 2; mt++)
#pragma unroll
            for (int nt = 0; nt < 3; nt++)
#pragma unroll
                for (int j = 0; j < 4; j++) acc[mt][nt][j] = 0.f;

        // prefetch chunk 0 (4 x 16B per plane per thread)
        uint4 pf[8];
        {
            const uint4* s0 = reinterpret_cast<const uint4*>(hhi + lrow * U_ + lkq);
            const uint4* s1 = reinterpret_cast<const uint4*>(hlo + lrow * U_ + lkq);
#pragma unroll
            for (int j = 0; j < 4; j++) { pf[j] = __ldcg(s0 + j); }
#pragma unroll
            for (int j = 0; j < 4; j++) { pf[4 + j] = __ldcg(s1 + j); }
        }

        for (int c = 0; c < 8; c++) {
            const int cb = c & 1;
            char* hb = smem + OFF_H + (size_t)(cb * 2) * HPLANE;
#pragma unroll
            for (int j = 0; j < 4; j++) {
                *reinterpret_cast<uint4*>(hb + h_st + j * 16) = pf[j];
                *reinterpret_cast<uint4*>(hb + HPLANE + h_st + j * 16) = pf[4 + j];
            }
            if (c < 7) {
                int k0 = (c + 1) * 128 + lkq;
                const uint4* s0 =
                    reinterpret_cast<const uint4*>(hhi + lrow * U_ + k0);
                const uint4* s1 =
                    reinterpret_cast<const uint4*>(hlo + lrow * U_ + k0);
#pragma unroll
                for (int j = 0; j < 4; j++) { pf[j] = __ldcg(s0 + j); }
#pragma unroll
                for (int j = 0; j < 4; j++) { pf[4 + j] = __ldcg(s1 + j); }
            }
            __syncthreads();

            // B fragments for this chunk & team: 32 k, reused across m-halves
            const uint32_t bbase =
                sb + OFF_W + (uint32_t)(c * 128 + tm * 32) * 2;
            uint32_t bhf[3][4], blf[3][4];
#pragma unroll
            for (int nt = 0; nt < 3; nt++) {
                ldsm_x4(bhf[nt], bbase + b_off[nt]);
                ldsm_x4(blf[nt], bbase + WPLANE + b_off[nt]);
            }
            const uint32_t abase = sb + OFF_H + (uint32_t)(cb * 2) * HPLANE +
                                   a_row_off + (uint32_t)(tm * 32) * 2;
#pragma unroll
            for (int mt = 0; mt < 2; mt++)
#pragma unroll
                for (int ks = 0; ks < 2; ks++) {
                    uint32_t ah[4], al[4];
                    ldsm_x4(ah, abase + mt * (16 * 272) + ks * 32);
                    ldsm_x4(al, abase + mt * (16 * 272) + ks * 32 + HPLANE);
#pragma unroll
                    for (int nt = 0; nt < 3; nt++) {
                        mma_bf16(acc[mt][nt], ah, &bhf[nt][ks * 2]);
                        mma_bf16(acc[mt][nt], al, &bhf[nt][ks * 2]);
                        mma_bf16(acc[mt][nt], ah, &blf[nt][ks * 2]);
                    }
                }
        }

        // write team-partial rec sums: recs[tm][n][row]
        {
            float* recT = recs + tm * RECF;
            int n = 2 * (lane & 3);
            int rowb = mh * 32 + (lane >> 2);
#pragma unroll
            for (int mt = 0; mt < 2; mt++) {
                int row = rowb + mt * 16;
#pragma unroll
                for (int nt = 0; nt < 3; nt++) {
                    int nb_ = nt * 8 + n;
                    recT[nb_ * 68 + row] = acc[mt][nt][0];
                    recT[(nb_ + 1) * 68 + row] = acc[mt][nt][1];
                    recT[nb_ * 68 + row + 8] = acc[mt][nt][2];
                    recT[(nb_ + 1) * 68 + row + 8] = acc[mt][nt][3];
                }
            }
        }
        __syncthreads();

        // gates: each thread does (grow, units gup, gup+1)
        const int nbuf = buf ^ 1;
        __nv_bfloat16* dhi = g_hbf[nbuf][0];
        __nv_bfloat16* dlo = g_hbf[nbuf][1];
        float hn[2];
        {
            const float* xp = &g_xproj[((size_t)grow * T_ + t) * N3_ + u0 + gup];
            float2 xz2 = *reinterpret_cast<const float2*>(xp);
            float2 xr2 = *reinterpret_cast<const float2*>(xp + U_);
            float2 xh2 = *reinterpret_cast<const float2*>(xp + 2 * U_);
#pragma unroll
            for (int j = 0; j < 2; j++) {
                int uu = gup + j;
                float rz = bhs[uu], rr = bhs[8 + uu], rh = bhs[16 + uu];
#pragma unroll
                for (int tt = 0; tt < 4; tt++) {
                    rz += recs[tt * RECF + uu * 68 + grow];
                    rr += recs[tt * RECF + (8 + uu) * 68 + grow];
                    rh += recs[tt * RECF + (16 + uu) * 68 + grow];
                }
                float xz = j ? xz2.y : xz2.x;
                float xr = j ? xr2.y : xr2.x;
                float xh = j ? xh2.y : xh2.x;
                float z = 1.f / (1.f + __expf(-(xz + rz)));
                float r = 1.f / (1.f + __expf(-(xr + rr)));
                float ca = xh + r * rh;
                float cand = 1.f - 2.f / (__expf(2.f * ca) + 1.f);
                hn[j] = z * hprev[j] + (1.f - z) * cand;
                hprev[j] = hn[j];
            }
            // store split-bf16 h (2 units packed per 4B per plane)
            __nv_bfloat16 h0 = __float2bfloat16(hn[0]);
            __nv_bfloat16 h1 = __float2bfloat16(hn[1]);
            __nv_bfloat16 l0 = __float2bfloat16(hn[0] - __bfloat162float(h0));
            __nv_bfloat16 l1 = __float2bfloat16(hn[1] - __bfloat162float(h1));
            unsigned phi = ((unsigned)__bfloat16_as_ushort(h1) << 16) |
                           __bfloat16_as_ushort(h0);
            unsigned plo = ((unsigned)__bfloat16_as_ushort(l1) << 16) |
                           __bfloat16_as_ushort(l0);
            int hidx = grow * U_ + u0 + gup;
            __stcg(reinterpret_cast<unsigned*>(&dhi[hidx]), phi);
            __stcg(reinterpret_cast<unsigned*>(&dlo[hidx]), plo);
        }

        // grid barrier; out-stores overlap the spin
        __threadfence();
        __syncthreads();
        if (tid == 0) atomicAdd(&g_bar, 1u);
        {
            float2 o2 = make_float2(hn[0], hn[1]);
            *reinterpret_cast<float2*>(
                &out[((size_t)grow * T_ + t) * U_ + u0 + gup]) = o2;
            if (t == T_ - 1)
                *reinterpret_cast<float2*>(
                    &out[(size_t)B_ * T_ * U_ + (size_t)grow * U_ + u0 + gup]) = o2;
        }
        if (tid == 0) {
            unsigned target = (unsigned)(NBLK * (t + 1));
            while (*((volatile unsigned*)&g_bar) < target) { }
        }
        __syncthreads();
    }
}

// ----------------- launch ---------------------------------------------------
extern "C" void kernel_launch(void* const* d_in, const int* in_sizes, int n_in,
                              void* d_out, int out_size) {
    const int* tokens = (const int*)d_in[0];
    const float* hidden = (const float*)d_in[1];
    const float* emb = (const float*)d_in[2];
    const float* Wx = (const float*)d_in[3];
    const float* bx = (const float*)d_in[4];
    const float* Wh = (const float*)d_in[5];
    const float* bh = (const float*)d_in[6];
    float* out = (float*)d_out;
    (void)in_sizes; (void)n_in; (void)out_size;

    cudaFuncSetAttribute(k_scan, cudaFuncAttributeMaxDynamicSharedMemorySize,
                         SCAN_SMEM);
    cudaFuncSetAttribute(k_xproj_tc, cudaFuncAttributeMaxDynamicSharedMemorySize,
                         XP_SMEM);

    k_init<<<(B_ * U_ + 255) / 256, 256>>>(hidden);
    k_prep<<<1024, 256>>>(emb, Wx);
    dim3 gx(N3_ / 64, (B_ * T_) / 128);
    k_xproj_tc<<<gx, 256, XP_SMEM>>>(tokens, bx);
    k_scan<<<NBLK, SCTH, SCAN_SMEM>>>(Wh, bh, hidden, out);
}

// round 12
// speedup vs baseline: 4.3537x; 1.8021x over previous
#include <cuda_runtime.h>
#include <cuda_bf16.h>
#include <cstdint>

// Problem constants
#define B_  64
#define T_  256
#define E_  512
#define U_  1024
#define N3_ 3072

#define NBLK 128          // scan grid (1 block/SM, all resident -> barrier safe)
#define UPB  8            // GRU units per scan block
#define SCTH 256          // 8 warps: 4 k-teams x 2 m-halves

// ---- scan smem layout (bytes) ----
#define WPLANE 49536                 // [24 n][1032 halves] stride 2064B
#define OFF_W    0                   // 2 planes (hi, lo)
#define OFF_RECS 99072               // [4 teams][24 n][68 floats]
#define RECF     1632                // floats per team
#define OFF_BHS  125184
#define SCAN_SMEM 125312

// ---- xproj smem layout (bytes) ----
#define XP_TOK  0                    // 128 ints
#define XP_A    512                  // [3 stages][2 planes][128 rows * 48B]
#define XP_APLANE 6144
#define XP_B    37376                // [3 stages][2 planes][64 rows * 48B]
#define XP_BPLANE 3072
#define XP_SMEM 55808

// ----------------- device scratch (no allocations allowed) -----------------
__device__ float g_xproj[(size_t)B_ * T_ * N3_];          // [B*T][3U] incl. bx
// h in MMA A-fragment order: [buf][plane][slot u32]
// slot = ((K*4 + mt)*32 + lane)*4 + reg,  K=k>>4 (64), mt=row>>4 (4)
__device__ uint32_t g_hA[2][2][32768];
__device__ __nv_bfloat16 g_embh[(size_t)32000 * E_];      // [tok][k]
__device__ __nv_bfloat16 g_embl[(size_t)32000 * E_];
__device__ __nv_bfloat16 g_wxh[(size_t)N3_ * E_];         // TRANSPOSED [n][k]
__device__ __nv_bfloat16 g_wxl[(size_t)N3_ * E_];
__device__ unsigned g_bar;

// ----------------- ptx helpers ---------------------------------------------
__device__ __forceinline__ uint32_t smem_u32(const void* p) {
    uint32_t a;
    asm("{ .reg .u64 t; cvta.to.shared.u64 t, %1; cvt.u32.u64 %0, t; }"
        : "=r"(a) : "l"(p));
    return a;
}
__device__ __forceinline__ void ldsm_x4(uint32_t* r, uint32_t addr) {
    asm volatile("ldmatrix.sync.aligned.m8n8.x4.shared.b16 {%0,%1,%2,%3}, [%4];"
                 : "=r"(r[0]), "=r"(r[1]), "=r"(r[2]), "=r"(r[3]) : "r"(addr));
}
__device__ __forceinline__ void mma_bf16(float* d, const uint32_t* a,
                                         const uint32_t* b) {
    asm volatile(
        "mma.sync.aligned.m16n8k16.row.col.f32.bf16.bf16.f32 "
        "{%0,%1,%2,%3}, {%4,%5,%6,%7}, {%8,%9}, {%0,%1,%2,%3};"
        : "+f"(d[0]), "+f"(d[1]), "+f"(d[2]), "+f"(d[3])
        : "r"(a[0]), "r"(a[1]), "r"(a[2]), "r"(a[3]), "r"(b[0]), "r"(b[1]));
}
__device__ __forceinline__ void cpa16(uint32_t dst, const void* src) {
    asm volatile("cp.async.cg.shared.global [%0], [%1], 16;"
                 :: "r"(dst), "l"(src) : "memory");
}
__device__ __forceinline__ void cpa_commit() {
    asm volatile("cp.async.commit_group;" ::: "memory");
}
template <int N>
__device__ __forceinline__ void cpa_wait() {
    asm volatile("cp.async.wait_group %0;" :: "n"(N) : "memory");
}

// load one chunk's A fragments (8 x LDG.128) straight into registers
__device__ __forceinline__ void lda_chunk(uint4* dst, int c, int tm, int mh,
                                          int lane, const uint4* h0,
                                          const uint4* h1) {
#pragma unroll
    for (int mtl = 0; mtl < 2; mtl++)
#pragma unroll
        for (int ks = 0; ks < 2; ks++) {
            int idx = (((c * 8 + tm * 2 + ks) * 4) + (2 * mh + mtl)) * 32 + lane;
            dst[mtl * 4 + ks * 2 + 0] = __ldcg(h0 + idx);
            dst[mtl * 4 + ks * 2 + 1] = __ldcg(h1 + idx);
        }
}

// ----------------- init: reset barrier + h0 -> fragment-ordered bf16 -------
__global__ void k_init(const float* __restrict__ hidden) {
    int idx = blockIdx.x * blockDim.x + threadIdx.x;
    if (idx == 0) g_bar = 0u;
    if (idx < B_ * U_) {
        int row = idx >> 10;
        int k = idx & (U_ - 1);
        float h = hidden[idx];
        __nv_bfloat16 hi = __float2bfloat16(h);
        __nv_bfloat16 lo = __float2bfloat16(h - __bfloat162float(hi));
        int K = k >> 4, klo = k & 15, mt = row >> 4, r = row & 15;
        int lane = (r & 7) * 4 + ((klo >> 1) & 3);
        int reg = (r >> 3) + 2 * (klo >> 3);
        int slot = ((K * 4 + mt) * 32 + lane) * 4 + reg;
        reinterpret_cast<unsigned short*>(&g_hA[0][0][slot])[klo & 1] =
            __bfloat16_as_ushort(hi);
        reinterpret_cast<unsigned short*>(&g_hA[0][1][slot])[klo & 1] =
            __bfloat16_as_ushort(lo);
    }
}

// ----------------- prep: split emb (as-is) and Wx (TRANSPOSED) -------------
__global__ void k_prep(const float* __restrict__ emb,
                       const float* __restrict__ Wx) {
    const size_t n1 = (size_t)32000 * E_;
    const size_t n2 = (size_t)N3_ * E_;
    for (size_t i = (size_t)blockIdx.x * blockDim.x + threadIdx.x; i < n1 + n2;
         i += (size_t)gridDim.x * blockDim.x) {
        if (i < n1) {
            float v = emb[i];
            __nv_bfloat16 hi = __float2bfloat16(v);
            g_embh[i] = hi;
            g_embl[i] = __float2bfloat16(v - __bfloat162float(hi));
        } else {
            size_t j = i - n1;          // j = n * E + k  (transposed layout)
            int n = (int)(j >> 9);
            int k = (int)(j & (E_ - 1));
            float v = Wx[(size_t)k * N3_ + n];
            __nv_bfloat16 hi = __float2bfloat16(v);
            g_wxh[j] = hi;
            g_wxl[j] = __float2bfloat16(v - __bfloat162float(hi));
        }
    }
}

// ----------------- kernel 1: tensor-core x_proj (round-8 proven) -----------
__global__ __launch_bounds__(256, 2)
void k_xproj_tc(const int* __restrict__ tokens, const float* __restrict__ bx) {
    extern __shared__ char xs[];
    const uint32_t sb = smem_u32(xs);
    const int tid = threadIdx.x;
    const int wid = tid >> 5;
    const int lane = tid & 31;
    const int n0 = blockIdx.x * 64;
    const int m0 = blockIdx.y * 128;

    int* toks = reinterpret_cast<int*>(xs + XP_TOK);
    if (tid < 128) toks[tid] = tokens[m0 + tid];
    __syncthreads();

    const int arow = tid >> 1, aseg = tid & 1;
    const size_t aoff = (size_t)toks[arow] * E_ + aseg * 8;
    const uint32_t adst = sb + XP_A + arow * 48 + aseg * 16;
    const int bplane = tid >> 7, b2 = tid & 127;
    const int brow = b2 >> 1, bseg = b2 & 1;
    const __nv_bfloat16* wsrc =
        (bplane ? g_wxl : g_wxh) + (size_t)(n0 + brow) * E_ + bseg * 8;
    const uint32_t bdst =
        sb + XP_B + bplane * XP_BPLANE + brow * 48 + bseg * 16;

#define XP_ISSUE(s, buf)                                               \
    {                                                                  \
        int k0_ = (s) * 16;                                            \
        cpa16(adst + (buf) * 12288, g_embh + aoff + k0_);              \
        cpa16(adst + (buf) * 12288 + XP_APLANE, g_embl + aoff + k0_);  \
        cpa16(bdst + (buf) * 6144, wsrc + k0_);                        \
        cpa_commit();                                                  \
    }

    const int mw = wid & 3, nw = wid >> 2;
    float acc[2][4][4];
#pragma unroll
    for (int mt = 0; mt < 2; mt++)
#pragma unroll
        for (int nt = 0; nt < 4; nt++)
#pragma unroll
            for (int j = 0; j < 4; j++) acc[mt][nt][j] = 0.f;

    const uint32_t a_off =
        (uint32_t)((mw * 32 + (lane & 15)) * 48 + ((lane >> 4) << 3) * 2);
    const uint32_t b_off =
        (uint32_t)((nw * 32 + (lane & 7) + ((lane >> 4) << 3)) * 48 +
                   (((lane >> 3) & 1) << 4));

    XP_ISSUE(0, 0);
    XP_ISSUE(1, 1);

    for (int s = 0; s < 32; s++) {
        const int buf = s % 3;
        cpa_wait<1>();
        __syncthreads();

        const uint32_t ab = sb + XP_A + buf * 12288 + a_off;
        const uint32_t bb = sb + XP_B + buf * 6144 + b_off;
        uint32_t ah[2][4], al[2][4], bhf[2][4], blf[2][4];
        ldsm_x4(ah[0], ab);
        ldsm_x4(ah[1], ab + 16 * 48);
        ldsm_x4(al[0], ab + XP_APLANE);
        ldsm_x4(al[1], ab + XP_APLANE + 16 * 48);
        ldsm_x4(bhf[0], bb);
        ldsm_x4(bhf[1], bb + 16 * 48);
        ldsm_x4(blf[0], bb + XP_BPLANE);
        ldsm_x4(blf[1], bb + XP_BPLANE + 16 * 48);

#pragma unroll
        for (int mt = 0; mt < 2; mt++)
#pragma unroll
            for (int nt = 0; nt < 4; nt++) {
                const uint32_t* fh = &bhf[nt >> 1][(nt & 1) * 2];
                const uint32_t* fl = &blf[nt >> 1][(nt & 1) * 2];
                mma_bf16(acc[mt][nt], ah[mt], fh);
                mma_bf16(acc[mt][nt], al[mt], fh);
                mma_bf16(acc[mt][nt], ah[mt], fl);
            }

        if (s + 2 < 32) XP_ISSUE(s + 2, (s + 2) % 3);
    }

    const int r0 = m0 + mw * 32 + (lane >> 2);
    const int c0 = n0 + nw * 32 + (lane & 3) * 2;
#pragma unroll
    for (int mt = 0; mt < 2; mt++)
#pragma unroll
        for (int nt = 0; nt < 4; nt++) {
            int rr = r0 + mt * 16, cc = c0 + nt * 8;
            float b0 = bx[cc], b1 = bx[cc + 1];
            float2 v0 = make_float2(acc[mt][nt][0] + b0, acc[mt][nt][1] + b1);
            float2 v1 = make_float2(acc[mt][nt][2] + b0, acc[mt][nt][3] + b1);
            *reinterpret_cast<float2*>(&g_xproj[(size_t)rr * N3_ + cc]) = v0;
            *reinterpret_cast<float2*>(&g_xproj[(size_t)(rr + 8) * N3_ + cc]) = v1;
        }
#undef XP_ISSUE
}

// ----------------- kernel 2: persistent mma.sync GRU scan ------------------
// h lives in global in MMA A-fragment order; consumers LDG.128 fragments
// straight into registers (no smem staging, no intra-step syncs in the
// chunk loop). Split-bf16 3-product numerics (round-8 proven).
__global__ __launch_bounds__(SCTH, 1)
void k_scan(const float* __restrict__ Wh, const float* __restrict__ bh,
            const float* __restrict__ hidden, float* __restrict__ out) {
    extern __shared__ __align__(128) char smem[];
    const uint32_t sb = smem_u32(smem);
    const int tid = threadIdx.x;
    const int wid = tid >> 5;
    const int lane = tid & 31;
    const int u0 = blockIdx.x * UPB;

    // ---- stage Wh columns as split-bf16 hi/lo ----
    for (int idx = tid; idx < 24 * 1024; idx += SCTH) {
        int n = idx >> 10, k = idx & 1023;
        int col = (n >> 3) * U_ + u0 + (n & 7);
        float w = Wh[(size_t)k * N3_ + col];
        __nv_bfloat16 whi = __float2bfloat16(w);
        __nv_bfloat16 wlo = __float2bfloat16(w - __bfloat162float(whi));
        int off = n * 2064 + k * 2;
        *reinterpret_cast<__nv_bfloat16*>(smem + OFF_W + off) = whi;
        *reinterpret_cast<__nv_bfloat16*>(smem + OFF_W + WPLANE + off) = wlo;
    }
    float* recs = reinterpret_cast<float*>(smem + OFF_RECS);
    float* bhs = reinterpret_cast<float*>(smem + OFF_BHS);
    if (tid < 24) bhs[tid] = bh[(tid >> 3) * U_ + u0 + (tid & 7)];

    // ---- warp geometry: 4 k-teams x 2 m-halves ----
    const int tm = wid & 3;          // k-team: 32 k per 128-chunk
    const int mh = wid >> 2;         // m-half: rows mh*32 .. +31

    uint32_t b_off[3];
#pragma unroll
    for (int nt = 0; nt < 3; nt++)
        b_off[nt] = (uint32_t)((nt * 8 + (lane & 7)) * 2064 +
                               (((lane >> 3) & 3) << 4));

    // gate mapping & producer slot (fragment-ordered h write)
    const int grow = tid >> 2;
    const int gup = (tid & 3) << 1;
    const int kk = u0 + gup;
    const int slot_p = ((((kk >> 4) * 4 + (grow >> 4)) * 32 +
                         ((grow & 7) * 4 + (((kk & 15) >> 1) & 3))) * 4) +
                       (((grow & 15) >> 3) + 2 * ((kk & 15) >> 3));

    float hprev[2];
    {
        const float2 h2 = *reinterpret_cast<const float2*>(
            &hidden[(size_t)grow * U_ + u0 + gup]);
        hprev[0] = h2.x;
        hprev[1] = h2.y;
    }
    __syncthreads();

    for (int t = 0; t < T_; t++) {
        const int buf = t & 1;
        const uint4* hA0 = reinterpret_cast<const uint4*>(g_hA[buf][0]);
        const uint4* hA1 = reinterpret_cast<const uint4*>(g_hA[buf][1]);

        float acc[2][3][4];
#pragma unroll
        for (int mt = 0; mt < 2; mt++)
#pragma unroll
            for (int nt = 0; nt < 3; nt++)
#pragma unroll
                for (int j = 0; j < 4; j++) acc[mt][nt][j] = 0.f;

        uint4 fa[2][8];                       // double-buffered A fragments
        lda_chunk(fa[0], 0, tm, mh, lane, hA0, hA1);

#pragma unroll
        for (int c = 0; c < 8; c++) {
            if (c < 7)
                lda_chunk(fa[(c + 1) & 1], c + 1, tm, mh, lane, hA0, hA1);

            const uint32_t bbase =
                sb + OFF_W + (uint32_t)(c * 128 + tm * 32) * 2;
            uint32_t bhf[3][4], blf[3][4];
#pragma unroll
            for (int nt = 0; nt < 3; nt++) {
                ldsm_x4(bhf[nt], bbase + b_off[nt]);
                ldsm_x4(blf[nt], bbase + WPLANE + b_off[nt]);
            }
            const uint4* cur = fa[c & 1];
#pragma unroll
            for (int mtl = 0; mtl < 2; mtl++)
#pragma unroll
                for (int ks = 0; ks < 2; ks++) {
                    const uint32_t* ah =
                        reinterpret_cast<const uint32_t*>(&cur[mtl * 4 + ks * 2]);
                    const uint32_t* al = reinterpret_cast<const uint32_t*>(
                        &cur[mtl * 4 + ks * 2 + 1]);
#pragma unroll
                    for (int nt = 0; nt < 3; nt++) {
                        mma_bf16(acc[mtl][nt], ah, &bhf[nt][ks * 2]);
                        mma_bf16(acc[mtl][nt], al, &bhf[nt][ks * 2]);
                        mma_bf16(acc[mtl][nt], ah, &blf[nt][ks * 2]);
                    }
                }
        }

        // write team-partial rec sums: recs[tm][n][row]
        {
            float* recT = recs + tm * RECF;
            int n = 2 * (lane & 3);
            int rowb = mh * 32 + (lane >> 2);
#pragma unroll
            for (int mt = 0; mt < 2; mt++) {
                int row = rowb + mt * 16;
#pragma unroll
                for (int nt = 0; nt < 3; nt++) {
                    int nb_ = nt * 8 + n;
                    recT[nb_ * 68 + row] = acc[mt][nt][0];
                    recT[(nb_ + 1) * 68 + row] = acc[mt][nt][1];
                    recT[nb_ * 68 + row + 8] = acc[mt][nt][2];
                    recT[(nb_ + 1) * 68 + row + 8] = acc[mt][nt][3];
                }
            }
        }
        __syncthreads();

        // gates: each thread does (grow, units gup, gup+1)
        const int nbuf = buf ^ 1;
        float hn[2];
        {
            const float* xp = &g_xproj[((size_t)grow * T_ + t) * N3_ + u0 + gup];
            float2 xz2 = *reinterpret_cast<const float2*>(xp);
            float2 xr2 = *reinterpret_cast<const float2*>(xp + U_);
            float2 xh2 = *reinterpret_cast<const float2*>(xp + 2 * U_);
#pragma unroll
            for (int j = 0; j < 2; j++) {
                int uu = gup + j;
                float rz = bhs[uu], rr = bhs[8 + uu], rh = bhs[16 + uu];
#pragma unroll
                for (int tt = 0; tt < 4; tt++) {
                    rz += recs[tt * RECF + uu * 68 + grow];
                    rr += recs[tt * RECF + (8 + uu) * 68 + grow];
                    rh += recs[tt * RECF + (16 + uu) * 68 + grow];
                }
                float xz = j ? xz2.y : xz2.x;
                float xr = j ? xr2.y : xr2.x;
                float xh = j ? xh2.y : xh2.x;
                float z = 1.f / (1.f + __expf(-(xz + rz)));
                float r = 1.f / (1.f + __expf(-(xr + rr)));
                float ca = xh + r * rh;
                float cand = 1.f - 2.f / (__expf(2.f * ca) + 1.f);
                hn[j] = z * hprev[j] + (1.f - z) * cand;
                hprev[j] = hn[j];
            }
            // store split-bf16 h in fragment order (1 u32 per plane)
            __nv_bfloat16 h0 = __float2bfloat16(hn[0]);
            __nv_bfloat16 h1 = __float2bfloat16(hn[1]);
            __nv_bfloat16 l0 = __float2bfloat16(hn[0] - __bfloat162float(h0));
            __nv_bfloat16 l1 = __float2bfloat16(hn[1] - __bfloat162float(h1));
            unsigned phi = ((unsigned)__bfloat16_as_ushort(h1) << 16) |
                           __bfloat16_as_ushort(h0);
            unsigned plo = ((unsigned)__bfloat16_as_ushort(l1) << 16) |
                           __bfloat16_as_ushort(l0);
            __stcg(&g_hA[nbuf][0][slot_p], phi);
            __stcg(&g_hA[nbuf][1][slot_p], plo);
        }

        // grid barrier; out-stores overlap the spin
        __threadfence();
        __syncthreads();
        if (tid == 0) atomicAdd(&g_bar, 1u);
        {
            float2 o2 = make_float2(hn[0], hn[1]);
            *reinterpret_cast<float2*>(
                &out[((size_t)grow * T_ + t) * U_ + u0 + gup]) = o2;
            if (t == T_ - 1)
                *reinterpret_cast<float2*>(
                    &out[(size_t)B_ * T_ * U_ + (size_t)grow * U_ + u0 + gup]) = o2;
        }
        if (tid == 0) {
            unsigned target = (unsigned)(NBLK * (t + 1));
            while (*((volatile unsigned*)&g_bar) < target) { }
        }
        __syncthreads();
    }
}

// ----------------- launch ---------------------------------------------------
extern "C" void kernel_launch(void* const* d_in, const int* in_sizes, int n_in,
                              void* d_out, int out_size) {
    const int* tokens = (const int*)d_in[0];
    const float* hidden = (const float*)d_in[1];
    const float* emb = (const float*)d_in[2];
    const float* Wx = (const float*)d_in[3];
    const float* bx = (const float*)d_in[4];
    const float* Wh = (const float*)d_in[5];
    const float* bh = (const float*)d_in[6];
    float* out = (float*)d_out;
    (void)in_sizes; (void)n_in; (void)out_size;

    cudaFuncSetAttribute(k_scan, cudaFuncAttributeMaxDynamicSharedMemorySize,
                         SCAN_SMEM);
    cudaFuncSetAttribute(k_xproj_tc, cudaFuncAttributeMaxDynamicSharedMemorySize,
                         XP_SMEM);

    k_init<<<(B_ * U_ + 255) / 256, 256>>>(hidden);
    k_prep<<<1024, 256>>>(emb, Wx);
    dim3 gx(N3_ / 64, (B_ * T_) / 128);
    k_xproj_tc<<<gx, 256, XP_SMEM>>>(tokens, bx);
    k_scan<<<NBLK, SCTH, SCAN_SMEM>>>(Wh, bh, hidden, out);
}

// round 13
// speedup vs baseline: 4.6296x; 1.0634x over previous
#include <cuda_runtime.h>
#include <cuda_bf16.h>
#include <cstdint>

// Problem constants
#define B_  64
#define T_  256
#define E_  512
#define U_  1024
#define N3_ 3072

#define NBLK 128          // scan grid (1 block/SM, all resident -> barrier safe)
#define UPB  8            // GRU units per scan block
#define SCTH 256          // 8 warps: 4 k-teams x 2 m-halves

// ---- scan smem layout (bytes) ----
#define WPLANE 49536                 // [24 n][1032 halves] stride 2064B
#define OFF_W    0                   // 2 planes (hi, lo)
#define OFF_RECS 99072               // [4 teams][24 n][68 floats]
#define RECF     1632                // floats per team
#define OFF_BHS  125184
#define SCAN_SMEM 125312

// ---- xproj smem layout (bytes) ----
#define XP_TOK  0                    // 128 ints
#define XP_A    512                  // [3 stages][2 planes][128 rows * 48B]
#define XP_APLANE 6144
#define XP_B    37376                // [3 stages][2 planes][64 rows * 48B]
#define XP_BPLANE 3072
#define XP_SMEM 55808

// ----------------- device scratch (no allocations allowed) -----------------
__device__ float g_xproj[(size_t)B_ * T_ * N3_];          // [B*T][3U] incl. bx
// h in MMA A-fragment order: [buf][plane][slot u32]
// slot = ((K*4 + mt)*32 + lane)*4 + reg,  K=k>>4 (64), mt=row>>4 (4)
__device__ uint32_t g_hA[2][2][32768];
__device__ __nv_bfloat16 g_embh[(size_t)32000 * E_];      // [tok][k]
__device__ __nv_bfloat16 g_embl[(size_t)32000 * E_];
__device__ __nv_bfloat16 g_wxh[(size_t)N3_ * E_];         // TRANSPOSED [n][k]
__device__ __nv_bfloat16 g_wxl[(size_t)N3_ * E_];
__device__ unsigned g_bar;

// ----------------- ptx helpers ---------------------------------------------
__device__ __forceinline__ uint32_t smem_u32(const void* p) {
    uint32_t a;
    asm("{ .reg .u64 t; cvta.to.shared.u64 t, %1; cvt.u32.u64 %0, t; }"
        : "=r"(a) : "l"(p));
    return a;
}
__device__ __forceinline__ void ldsm_x4(uint32_t* r, uint32_t addr) {
    asm volatile("ldmatrix.sync.aligned.m8n8.x4.shared.b16 {%0,%1,%2,%3}, [%4];"
                 : "=r"(r[0]), "=r"(r[1]), "=r"(r[2]), "=r"(r[3]) : "r"(addr));
}
__device__ __forceinline__ void mma_bf16(float* d, const uint32_t* a,
                                         const uint32_t* b) {
    asm volatile(
        "mma.sync.aligned.m16n8k16.row.col.f32.bf16.bf16.f32 "
        "{%0,%1,%2,%3}, {%4,%5,%6,%7}, {%8,%9}, {%0,%1,%2,%3};"
        : "+f"(d[0]), "+f"(d[1]), "+f"(d[2]), "+f"(d[3])
        : "r"(a[0]), "r"(a[1]), "r"(a[2]), "r"(a[3]), "r"(b[0]), "r"(b[1]));
}
__device__ __forceinline__ void cpa16(uint32_t dst, const void* src) {
    asm volatile("cp.async.cg.shared.global [%0], [%1], 16;"
                 :: "r"(dst), "l"(src) : "memory");
}
__device__ __forceinline__ void cpa_commit() {
    asm volatile("cp.async.commit_group;" ::: "memory");
}
template <int N>
__device__ __forceinline__ void cpa_wait() {
    asm volatile("cp.async.wait_group %0;" :: "n"(N) : "memory");
}

// load one chunk's A fragments (8 x LDG.128) straight into registers
__device__ __forceinline__ void lda_chunk(uint4* dst, int c, int tm, int mh,
                                          int lane, const uint4* h0,
                                          const uint4* h1) {
#pragma unroll
    for (int mtl = 0; mtl < 2; mtl++)
#pragma unroll
        for (int ks = 0; ks < 2; ks++) {
            int idx = (((c * 8 + tm * 2 + ks) * 4) + (2 * mh + mtl)) * 32 + lane;
            dst[mtl * 4 + ks * 2 + 0] = __ldcg(h0 + idx);
            dst[mtl * 4 + ks * 2 + 1] = __ldcg(h1 + idx);
        }
}

// ----------------- init: reset barrier + h0 -> fragment-ordered bf16 -------
__global__ void k_init(const float* __restrict__ hidden) {
    int idx = blockIdx.x * blockDim.x + threadIdx.x;
    if (idx == 0) g_bar = 0u;
    if (idx < B_ * U_) {
        int row = idx >> 10;
        int k = idx & (U_ - 1);
        float h = hidden[idx];
        __nv_bfloat16 hi = __float2bfloat16(h);
        __nv_bfloat16 lo = __float2bfloat16(h - __bfloat162float(hi));
        int K = k >> 4, klo = k & 15, mt = row >> 4, r = row & 15;
        int lane = (r & 7) * 4 + ((klo >> 1) & 3);
        int reg = (r >> 3) + 2 * (klo >> 3);
        int slot = ((K * 4 + mt) * 32 + lane) * 4 + reg;
        reinterpret_cast<unsigned short*>(&g_hA[0][0][slot])[klo & 1] =
            __bfloat16_as_ushort(hi);
        reinterpret_cast<unsigned short*>(&g_hA[0][1][slot])[klo & 1] =
            __bfloat16_as_ushort(lo);
    }
}

// ----------------- prep: split emb (as-is) and Wx (TRANSPOSED) -------------
__global__ void k_prep(const float* __restrict__ emb,
                       const float* __restrict__ Wx) {
    const size_t n1 = (size_t)32000 * E_;
    const size_t n2 = (size_t)N3_ * E_;
    for (size_t i = (size_t)blockIdx.x * blockDim.x + threadIdx.x; i < n1 + n2;
         i += (size_t)gridDim.x * blockDim.x) {
        if (i < n1) {
            float v = emb[i];
            __nv_bfloat16 hi = __float2bfloat16(v);
            g_embh[i] = hi;
            g_embl[i] = __float2bfloat16(v - __bfloat162float(hi));
        } else {
            size_t j = i - n1;          // j = n * E + k  (transposed layout)
            int n = (int)(j >> 9);
            int k = (int)(j & (E_ - 1));
            float v = Wx[(size_t)k * N3_ + n];
            __nv_bfloat16 hi = __float2bfloat16(v);
            g_wxh[j] = hi;
            g_wxl[j] = __float2bfloat16(v - __bfloat162float(hi));
        }
    }
}

// ----------------- kernel 1: tensor-core x_proj (round-8 proven) -----------
__global__ __launch_bounds__(256, 2)
void k_xproj_tc(const int* __restrict__ tokens, const float* __restrict__ bx) {
    extern __shared__ char xs[];
    const uint32_t sb = smem_u32(xs);
    const int tid = threadIdx.x;
    const int wid = tid >> 5;
    const int lane = tid & 31;
    const int n0 = blockIdx.x * 64;
    const int m0 = blockIdx.y * 128;

    int* toks = reinterpret_cast<int*>(xs + XP_TOK);
    if (tid < 128) toks[tid] = tokens[m0 + tid];
    __syncthreads();

    const int arow = tid >> 1, aseg = tid & 1;
    const size_t aoff = (size_t)toks[arow] * E_ + aseg * 8;
    const uint32_t adst = sb + XP_A + arow * 48 + aseg * 16;
    const int bplane = tid >> 7, b2 = tid & 127;
    const int brow = b2 >> 1, bseg = b2 & 1;
    const __nv_bfloat16* wsrc =
        (bplane ? g_wxl : g_wxh) + (size_t)(n0 + brow) * E_ + bseg * 8;
    const uint32_t bdst =
        sb + XP_B + bplane * XP_BPLANE + brow * 48 + bseg * 16;

#define XP_ISSUE(s, buf)                                               \
    {                                                                  \
        int k0_ = (s) * 16;                                            \
        cpa16(adst + (buf) * 12288, g_embh + aoff + k0_);              \
        cpa16(adst + (buf) * 12288 + XP_APLANE, g_embl + aoff + k0_);  \
        cpa16(bdst + (buf) * 6144, wsrc + k0_);                        \
        cpa_commit();                                                  \
    }

    const int mw = wid & 3, nw = wid >> 2;
    float acc[2][4][4];
#pragma unroll
    for (int mt = 0; mt < 2; mt++)
#pragma unroll
        for (int nt = 0; nt < 4; nt++)
#pragma unroll
            for (int j = 0; j < 4; j++) acc[mt][nt][j] = 0.f;

    const uint32_t a_off =
        (uint32_t)((mw * 32 + (lane & 15)) * 48 + ((lane >> 4) << 3) * 2);
    const uint32_t b_off =
        (uint32_t)((nw * 32 + (lane & 7) + ((lane >> 4) << 3)) * 48 +
                   (((lane >> 3) & 1) << 4));

    XP_ISSUE(0, 0);
    XP_ISSUE(1, 1);

    for (int s = 0; s < 32; s++) {
        const int buf = s % 3;
        cpa_wait<1>();
        __syncthreads();

        const uint32_t ab = sb + XP_A + buf * 12288 + a_off;
        const uint32_t bb = sb + XP_B + buf * 6144 + b_off;
        uint32_t ah[2][4], al[2][4], bhf[2][4], blf[2][4];
        ldsm_x4(ah[0], ab);
        ldsm_x4(ah[1], ab + 16 * 48);
        ldsm_x4(al[0], ab + XP_APLANE);
        ldsm_x4(al[1], ab + XP_APLANE + 16 * 48);
        ldsm_x4(bhf[0], bb);
        ldsm_x4(bhf[1], bb + 16 * 48);
        ldsm_x4(blf[0], bb + XP_BPLANE);
        ldsm_x4(blf[1], bb + XP_BPLANE + 16 * 48);

#pragma unroll
        for (int mt = 0; mt < 2; mt++)
#pragma unroll
            for (int nt = 0; nt < 4; nt++) {
                const uint32_t* fh = &bhf[nt >> 1][(nt & 1) * 2];
                const uint32_t* fl = &blf[nt >> 1][(nt & 1) * 2];
                mma_bf16(acc[mt][nt], ah[mt], fh);
                mma_bf16(acc[mt][nt], al[mt], fh);
                mma_bf16(acc[mt][nt], ah[mt], fl);
            }

        if (s + 2 < 32) XP_ISSUE(s + 2, (s + 2) % 3);
    }

    const int r0 = m0 + mw * 32 + (lane >> 2);
    const int c0 = n0 + nw * 32 + (lane & 3) * 2;
#pragma unroll
    for (int mt = 0; mt < 2; mt++)
#pragma unroll
        for (int nt = 0; nt < 4; nt++) {
            int rr = r0 + mt * 16, cc = c0 + nt * 8;
            float b0 = bx[cc], b1 = bx[cc + 1];
            float2 v0 = make_float2(acc[mt][nt][0] + b0, acc[mt][nt][1] + b1);
            float2 v1 = make_float2(acc[mt][nt][2] + b0, acc[mt][nt][3] + b1);
            *reinterpret_cast<float2*>(&g_xproj[(size_t)rr * N3_ + cc]) = v0;
            *reinterpret_cast<float2*>(&g_xproj[(size_t)(rr + 8) * N3_ + cc]) = v1;
        }
#undef XP_ISSUE
}

// ----------------- kernel 2: persistent mma.sync GRU scan ------------------
// h in global in MMA A-fragment order; LDG.128 fragments straight into
// registers, 2-chunk-deep pipeline. Gate xp loads hoisted to step start.
__global__ __launch_bounds__(SCTH, 1)
void k_scan(const float* __restrict__ Wh, const float* __restrict__ bh,
            const float* __restrict__ hidden, float* __restrict__ out) {
    extern __shared__ __align__(128) char smem[];
    const uint32_t sb = smem_u32(smem);
    const int tid = threadIdx.x;
    const int wid = tid >> 5;
    const int lane = tid & 31;
    const int u0 = blockIdx.x * UPB;

    // ---- stage Wh columns as split-bf16 hi/lo ----
    for (int idx = tid; idx < 24 * 1024; idx += SCTH) {
        int n = idx >> 10, k = idx & 1023;
        int col = (n >> 3) * U_ + u0 + (n & 7);
        float w = Wh[(size_t)k * N3_ + col];
        __nv_bfloat16 whi = __float2bfloat16(w);
        __nv_bfloat16 wlo = __float2bfloat16(w - __bfloat162float(whi));
        int off = n * 2064 + k * 2;
        *reinterpret_cast<__nv_bfloat16*>(smem + OFF_W + off) = whi;
        *reinterpret_cast<__nv_bfloat16*>(smem + OFF_W + WPLANE + off) = wlo;
    }
    float* recs = reinterpret_cast<float*>(smem + OFF_RECS);
    float* bhs = reinterpret_cast<float*>(smem + OFF_BHS);
    if (tid < 24) bhs[tid] = bh[(tid >> 3) * U_ + u0 + (tid & 7)];

    // ---- warp geometry: 4 k-teams x 2 m-halves ----
    const int tm = wid & 3;          // k-team: 32 k per 128-chunk
    const int mh = wid >> 2;         // m-half: rows mh*32 .. +31

    uint32_t b_off[3];
#pragma unroll
    for (int nt = 0; nt < 3; nt++)
        b_off[nt] = (uint32_t)((nt * 8 + (lane & 7)) * 2064 +
                               (((lane >> 3) & 3) << 4));

    // gate mapping & producer slot (fragment-ordered h write)
    const int grow = tid >> 2;
    const int gup = (tid & 3) << 1;
    const int kk = u0 + gup;
    const int slot_p = ((((kk >> 4) * 4 + (grow >> 4)) * 32 +
                         ((grow & 7) * 4 + (((kk & 15) >> 1) & 3))) * 4) +
                       (((grow & 15) >> 3) + 2 * ((kk & 15) >> 3));

    float hprev[2];
    {
        const float2 h2 = *reinterpret_cast<const float2*>(
            &hidden[(size_t)grow * U_ + u0 + gup]);
        hprev[0] = h2.x;
        hprev[1] = h2.y;
    }
    __syncthreads();

    for (int t = 0; t < T_; t++) {
        const int buf = t & 1;
        const uint4* hA0 = reinterpret_cast<const uint4*>(g_hA[buf][0]);
        const uint4* hA1 = reinterpret_cast<const uint4*>(g_hA[buf][1]);

        // hoisted gate xp loads (independent of h -> issue first)
        float2 xz2, xr2, xh2;
        {
            const float* xp =
                &g_xproj[((size_t)grow * T_ + t) * N3_ + u0 + gup];
            xz2 = __ldg(reinterpret_cast<const float2*>(xp));
            xr2 = __ldg(reinterpret_cast<const float2*>(xp + U_));
            xh2 = __ldg(reinterpret_cast<const float2*>(xp + 2 * U_));
        }

        float acc[2][3][4];
#pragma unroll
        for (int mt = 0; mt < 2; mt++)
#pragma unroll
            for (int nt = 0; nt < 3; nt++)
#pragma unroll
                for (int j = 0; j < 4; j++) acc[mt][nt][j] = 0.f;

        uint4 fa[3][8];                       // 2-deep A fragment pipeline
        lda_chunk(fa[0], 0, tm, mh, lane, hA0, hA1);
        lda_chunk(fa[1], 1, tm, mh, lane, hA0, hA1);

#pragma unroll
        for (int c = 0; c < 8; c++) {
            if (c < 6)
                lda_chunk(fa[(c + 2) % 3], c + 2, tm, mh, lane, hA0, hA1);

            const uint32_t bbase =
                sb + OFF_W + (uint32_t)(c * 128 + tm * 32) * 2;
            uint32_t bhf[3][4], blf[3][4];
#pragma unroll
            for (int nt = 0; nt < 3; nt++) {
                ldsm_x4(bhf[nt], bbase + b_off[nt]);
                ldsm_x4(blf[nt], bbase + WPLANE + b_off[nt]);
            }
            const uint4* cur = fa[c % 3];
#pragma unroll
            for (int mtl = 0; mtl < 2; mtl++)
#pragma unroll
                for (int ks = 0; ks < 2; ks++) {
                    const uint32_t* ah =
                        reinterpret_cast<const uint32_t*>(&cur[mtl * 4 + ks * 2]);
                    const uint32_t* al = reinterpret_cast<const uint32_t*>(
                        &cur[mtl * 4 + ks * 2 + 1]);
#pragma unroll
                    for (int nt = 0; nt < 3; nt++) {
                        mma_bf16(acc[mtl][nt], ah, &bhf[nt][ks * 2]);
                        mma_bf16(acc[mtl][nt], al, &bhf[nt][ks * 2]);
                        mma_bf16(acc[mtl][nt], ah, &blf[nt][ks * 2]);
                    }
                }
        }

        // write team-partial rec sums: recs[tm][n][row]
        {
            float* recT = recs + tm * RECF;
            int n = 2 * (lane & 3);
            int rowb = mh * 32 + (lane >> 2);
#pragma unroll
            for (int mt = 0; mt < 2; mt++) {
                int row = rowb + mt * 16;
#pragma unroll
                for (int nt = 0; nt < 3; nt++) {
                    int nb_ = nt * 8 + n;
                    recT[nb_ * 68 + row] = acc[mt][nt][0];
                    recT[(nb_ + 1) * 68 + row] = acc[mt][nt][1];
                    recT[nb_ * 68 + row + 8] = acc[mt][nt][2];
                    recT[(nb_ + 1) * 68 + row + 8] = acc[mt][nt][3];
                }
            }
        }
        __syncthreads();

        // gates: each thread does (grow, units gup, gup+1)
        const int nbuf = buf ^ 1;
        float hn[2];
        {
#pragma unroll
            for (int j = 0; j < 2; j++) {
                int uu = gup + j;
                float rz = bhs[uu], rr = bhs[8 + uu], rh = bhs[16 + uu];
#pragma unroll
                for (int tt = 0; tt < 4; tt++) {
                    rz += recs[tt * RECF + uu * 68 + grow];
                    rr += recs[tt * RECF + (8 + uu) * 68 + grow];
                    rh += recs[tt * RECF + (16 + uu) * 68 + grow];
                }
                float xz = j ? xz2.y : xz2.x;
                float xr = j ? xr2.y : xr2.x;
                float xh = j ? xh2.y : xh2.x;
                float z = 1.f / (1.f + __expf(-(xz + rz)));
                float r = 1.f / (1.f + __expf(-(xr + rr)));
                float ca = xh + r * rh;
                float cand = 1.f - 2.f / (__expf(2.f * ca) + 1.f);
                hn[j] = z * hprev[j] + (1.f - z) * cand;
                hprev[j] = hn[j];
            }
            // store split-bf16 h in fragment order (1 u32 per plane)
            __nv_bfloat16 h0 = __float2bfloat16(hn[0]);
            __nv_bfloat16 h1 = __float2bfloat16(hn[1]);
            __nv_bfloat16 l0 = __float2bfloat16(hn[0] - __bfloat162float(h0));
            __nv_bfloat16 l1 = __float2bfloat16(hn[1] - __bfloat162float(h1));
            unsigned phi = ((unsigned)__bfloat16_as_ushort(h1) << 16) |
                           __bfloat16_as_ushort(h0);
            unsigned plo = ((unsigned)__bfloat16_as_ushort(l1) << 16) |
                           __bfloat16_as_ushort(l0);
            __stcg(&g_hA[nbuf][0][slot_p], phi);
            __stcg(&g_hA[nbuf][1][slot_p], plo);
        }

        // grid barrier; out-stores overlap the spin
        __threadfence();
        __syncthreads();
        if (tid == 0) atomicAdd(&g_bar, 1u);
        {
            float2 o2 = make_float2(hn[0], hn[1]);
            *reinterpret_cast<float2*>(
                &out[((size_t)grow * T_ + t) * U_ + u0 + gup]) = o2;
            if (t == T_ - 1)
                *reinterpret_cast<float2*>(
                    &out[(size_t)B_ * T_ * U_ + (size_t)grow * U_ + u0 + gup]) = o2;
        }
        if (tid == 0) {
            unsigned target = (unsigned)(NBLK * (t + 1));
            while (*((volatile unsigned*)&g_bar) < target) { }
        }
        __syncthreads();
    }
}

// ----------------- launch ---------------------------------------------------
extern "C" void kernel_launch(void* const* d_in, const int* in_sizes, int n_in,
                              void* d_out, int out_size) {
    const int* tokens = (const int*)d_in[0];
    const float* hidden = (const float*)d_in[1];
    const float* emb = (const float*)d_in[2];
    const float* Wx = (const float*)d_in[3];
    const float* bx = (const float*)d_in[4];
    const float* Wh = (const float*)d_in[5];
    const float* bh = (const float*)d_in[6];
    float* out = (float*)d_out;
    (void)in_sizes; (void)n_in; (void)out_size;

    cudaFuncSetAttribute(k_scan, cudaFuncAttributeMaxDynamicSharedMemorySize,
                         SCAN_SMEM);
    cudaFuncSetAttribute(k_xproj_tc, cudaFuncAttributeMaxDynamicSharedMemorySize,
                         XP_SMEM);

    k_init<<<(B_ * U_ + 255) / 256, 256>>>(hidden);
    k_prep<<<1024, 256>>>(emb, Wx);
    dim3 gx(N3_ / 64, (B_ * T_) / 128);
    k_xproj_tc<<<gx, 256, XP_SMEM>>>(tokens, bx);
    k_scan<<<NBLK, SCTH, SCAN_SMEM>>>(Wh, bh, hidden, out);
}

// round 15
// speedup vs baseline: 5.3161x; 1.1483x over previous
#include <cuda_runtime.h>
#include <cuda_bf16.h>
#include <cuda_fp16.h>
#include <cstdint>

// Problem constants
#define B_  64
#define T_  256
#define E_  512
#define U_  1024
#define N3_ 3072

#define NBLK 128          // scan grid (1 block/SM, all resident -> barrier safe)
#define UPB  8            // GRU units per scan block
#define SCTH 256          // 8 warps: 4 k-teams x 2 m-halves

#define WLO_SCALE 1024.0f  // keeps fp16 W-residuals out of subnormal range

// ---- scan smem layout (bytes) ----
#define WPLANE 49536                 // [24 n][1032 halves] stride 2064B
#define OFF_W    0                   // 2 planes (hi, lo*1024)
#define OFF_RECS 99072               // [4 teams][24 n][68 floats]
#define RECF     1632                // floats per team
#define OFF_BHS  125184
#define SCAN_SMEM 125312

// ---- xproj smem layout (bytes) ----
#define XP_TOK  0                    // 128 ints
#define XP_A    512                  // [3 stages][2 planes][128 rows * 48B]
#define XP_APLANE 6144
#define XP_B    37376                // [3 stages][2 planes][64 rows * 48B]
#define XP_BPLANE 3072
#define XP_SMEM 55808

// ----------------- device scratch (no allocations allowed) -----------------
__device__ float g_xproj[(size_t)B_ * T_ * N3_];          // [B*T][3U] incl. bx
// h (fp16, single plane) in MMA A-fragment order: [buf][slot u32]
// slot = ((K*4 + mt)*32 + lane)*4 + reg,  K=k>>4 (64), mt=row>>4 (4)
__device__ uint32_t g_hA[2][32768];
__device__ __nv_bfloat16 g_embh[(size_t)32000 * E_];      // [tok][k]
__device__ __nv_bfloat16 g_embl[(size_t)32000 * E_];
__device__ __nv_bfloat16 g_wxh[(size_t)N3_ * E_];         // TRANSPOSED [n][k]
__device__ __nv_bfloat16 g_wxl[(size_t)N3_ * E_];
__device__ unsigned g_bar;

// ----------------- ptx helpers ---------------------------------------------
__device__ __forceinline__ uint32_t smem_u32(const void* p) {
    uint32_t a;
    asm("{ .reg .u64 t; cvta.to.shared.u64 t, %1; cvt.u32.u64 %0, t; }"
        : "=r"(a) : "l"(p));
    return a;
}
__device__ __forceinline__ void ldsm_x4(uint32_t* r, uint32_t addr) {
    asm volatile("ldmatrix.sync.aligned.m8n8.x4.shared.b16 {%0,%1,%2,%3}, [%4];"
                 : "=r"(r[0]), "=r"(r[1]), "=r"(r[2]), "=r"(r[3]) : "r"(addr));
}
__device__ __forceinline__ void mma_bf16(float* d, const uint32_t* a,
                                         const uint32_t* b) {
    asm volatile(
        "mma.sync.aligned.m16n8k16.row.col.f32.bf16.bf16.f32 "
        "{%0,%1,%2,%3}, {%4,%5,%6,%7}, {%8,%9}, {%0,%1,%2,%3};"
        : "+f"(d[0]), "+f"(d[1]), "+f"(d[2]), "+f"(d[3])
        : "r"(a[0]), "r"(a[1]), "r"(a[2]), "r"(a[3]), "r"(b[0]), "r"(b[1]));
}
__device__ __forceinline__ void mma_f16(float* d, const uint32_t* a,
                                        const uint32_t* b) {
    asm volatile(
        "mma.sync.aligned.m16n8k16.row.col.f32.f16.f16.f32 "
        "{%0,%1,%2,%3}, {%4,%5,%6,%7}, {%8,%9}, {%0,%1,%2,%3};"
        : "+f"(d[0]), "+f"(d[1]), "+f"(d[2]), "+f"(d[3])
        : "r"(a[0]), "r"(a[1]), "r"(a[2]), "r"(a[3]), "r"(b[0]), "r"(b[1]));
}
__device__ __forceinline__ void cpa16(uint32_t dst, const void* src) {
    asm volatile("cp.async.cg.shared.global [%0], [%1], 16;"
                 :: "r"(dst), "l"(src) : "memory");
}
__device__ __forceinline__ void cpa_commit() {
    asm volatile("cp.async.commit_group;" ::: "memory");
}
template <int N>
__device__ __forceinline__ void cpa_wait() {
    asm volatile("cp.async.wait_group %0;" :: "n"(N) : "memory");
}

// load one chunk's A fragments (4 x LDG.128) straight into registers
__device__ __forceinline__ void lda_chunk(uint4* dst, int c, int tm, int mh,
                                          int lane, const uint4* h0) {
#pragma unroll
    for (int mtl = 0; mtl < 2; mtl++)
#pragma unroll
        for (int ks = 0; ks < 2; ks++) {
            int idx = (((c * 8 + tm * 2 + ks) * 4) + (2 * mh + mtl)) * 32 + lane;
            dst[mtl * 2 + ks] = __ldcg(h0 + idx);
        }
}

// ----------------- init: reset barrier + h0 -> fragment-ordered fp16 -------
__global__ void k_init(const float* __restrict__ hidden) {
    int idx = blockIdx.x * blockDim.x + threadIdx.x;
    if (idx == 0) g_bar = 0u;
    if (idx < B_ * U_) {
        int row = idx >> 10;
        int k = idx & (U_ - 1);
        __half h = __float2half_rn(hidden[idx]);
        int K = k >> 4, klo = k & 15, mt = row >> 4, r = row & 15;
        int lane = (r & 7) * 4 + ((klo >> 1) & 3);
        int reg = (r >> 3) + 2 * (klo >> 3);
        int slot = ((K * 4 + mt) * 32 + lane) * 4 + reg;
        reinterpret_cast<unsigned short*>(&g_hA[0][slot])[klo & 1] =
            __half_as_ushort(h);
    }
}

// ----------------- prep: split emb (as-is) and Wx (TRANSPOSED) -------------
__global__ void k_prep(const float* __restrict__ emb,
                       const float* __restrict__ Wx) {
    const size_t n1 = (size_t)32000 * E_;
    const size_t n2 = (size_t)N3_ * E_;
    for (size_t i = (size_t)blockIdx.x * blockDim.x + threadIdx.x; i < n1 + n2;
         i += (size_t)gridDim.x * blockDim.x) {
        if (i < n1) {
            float v = emb[i];
            __nv_bfloat16 hi = __float2bfloat16(v);
            g_embh[i] = hi;
            g_embl[i] = __float2bfloat16(v - __bfloat162float(hi));
        } else {
            size_t j = i - n1;          // j = n * E + k  (transposed layout)
            int n = (int)(j >> 9);
            int k = (int)(j & (E_ - 1));
            float v = Wx[(size_t)k * N3_ + n];
            __nv_bfloat16 hi = __float2bfloat16(v);
            g_wxh[j] = hi;
            g_wxl[j] = __float2bfloat16(v - __bfloat162float(hi));
        }
    }
}

// ----------------- kernel 1: tensor-core x_proj (round-8 proven) -----------
__global__ __launch_bounds__(256, 2)
void k_xproj_tc(const int* __restrict__ tokens, const float* __restrict__ bx) {
    extern __shared__ char xs[];
    const uint32_t sb = smem_u32(xs);
    const int tid = threadIdx.x;
    const int wid = tid >> 5;
    const int lane = tid & 31;
    const int n0 = blockIdx.x * 64;
    const int m0 = blockIdx.y * 128;

    int* toks = reinterpret_cast<int*>(xs + XP_TOK);
    if (tid < 128) toks[tid] = tokens[m0 + tid];
    __syncthreads();

    const int arow = tid >> 1, aseg = tid & 1;
    const size_t aoff = (size_t)toks[arow] * E_ + aseg * 8;
    const uint32_t adst = sb + XP_A + arow * 48 + aseg * 16;
    const int bplane = tid >> 7, b2 = tid & 127;
    const int brow = b2 >> 1, bseg = b2 & 1;
    const __nv_bfloat16* wsrc =
        (bplane ? g_wxl : g_wxh) + (size_t)(n0 + brow) * E_ + bseg * 8;
    const uint32_t bdst =
        sb + XP_B + bplane * XP_BPLANE + brow * 48 + bseg * 16;

#define XP_ISSUE(s, buf)                                               \
    {                                                                  \
        int k0_ = (s) * 16;                                            \
        cpa16(adst + (buf) * 12288, g_embh + aoff + k0_);              \
        cpa16(adst + (buf) * 12288 + XP_APLANE, g_embl + aoff + k0_);  \
        cpa16(bdst + (buf) * 6144, wsrc + k0_);                        \
        cpa_commit();                                                  \
    }

    const int mw = wid & 3, nw = wid >> 2;
    float acc[2][4][4];
#pragma unroll
    for (int mt = 0; mt < 2; mt++)
#pragma unroll
        for (int nt = 0; nt < 4; nt++)
#pragma unroll
            for (int j = 0; j < 4; j++) acc[mt][nt][j] = 0.f;

    const uint32_t a_off =
        (uint32_t)((mw * 32 + (lane & 15)) * 48 + ((lane >> 4) << 3) * 2);
    const uint32_t b_off =
        (uint32_t)((nw * 32 + (lane & 7) + ((lane >> 4) << 3)) * 48 +
                   (((lane >> 3) & 1) << 4));

    XP_ISSUE(0, 0);
    XP_ISSUE(1, 1);

    for (int s = 0; s < 32; s++) {
        const int buf = s % 3;
        cpa_wait<1>();
        __syncthreads();

        const uint32_t ab = sb + XP_A + buf * 12288 + a_off;
        const uint32_t bb = sb + XP_B + buf * 6144 + b_off;
        uint32_t ah[2][4], al[2][4], bhf[2][4], blf[2][4];
        ldsm_x4(ah[0], ab);
        ldsm_x4(ah[1], ab + 16 * 48);
        ldsm_x4(al[0], ab + XP_APLANE);
        ldsm_x4(al[1], ab + XP_APLANE + 16 * 48);
        ldsm_x4(bhf[0], bb);
        ldsm_x4(bhf[1], bb + 16 * 48);
        ldsm_x4(blf[0], bb + XP_BPLANE);
        ldsm_x4(blf[1], bb + XP_BPLANE + 16 * 48);

#pragma unroll
        for (int mt = 0; mt < 2; mt++)
#pragma unroll
            for (int nt = 0; nt < 4; nt++) {
                const uint32_t* fh = &bhf[nt >> 1][(nt & 1) * 2];
                const uint32_t* fl = &blf[nt >> 1][(nt & 1) * 2];
                mma_bf16(acc[mt][nt], ah[mt], fh);
                mma_bf16(acc[mt][nt], al[mt], fh);
                mma_bf16(acc[mt][nt], ah[mt], fl);
            }

        if (s + 2 < 32) XP_ISSUE(s + 2, (s + 2) % 3);
    }

    const int r0 = m0 + mw * 32 + (lane >> 2);
    const int c0 = n0 + nw * 32 + (lane & 3) * 2;
#pragma unroll
    for (int mt = 0; mt < 2; mt++)
#pragma unroll
        for (int nt = 0; nt < 4; nt++) {
            int rr = r0 + mt * 16, cc = c0 + nt * 8;
            float b0 = bx[cc], b1 = bx[cc + 1];
            float2 v0 = make_float2(acc[mt][nt][0] + b0, acc[mt][nt][1] + b1);
            float2 v1 = make_float2(acc[mt][nt][2] + b0, acc[mt][nt][3] + b1);
            *reinterpret_cast<float2*>(&g_xproj[(size_t)rr * N3_ + cc]) = v0;
            *reinterpret_cast<float2*>(&g_xproj[(size_t)(rr + 8) * N3_ + cc]) = v1;
        }
#undef XP_ISSUE
}

// ----------------- kernel 2: persistent mma.sync GRU scan ------------------
// h (fp16, single plane) in global in MMA A-fragment order. Wh split-fp16
// with lo plane scaled x1024 (subnormal-safe), separate accumulator,
// combined as acc + acc2/1024. 2-chunk-deep LDG pipeline.
__global__ __launch_bounds__(SCTH, 1)
void k_scan(const float* __restrict__ Wh, const float* __restrict__ bh,
            const float* __restrict__ hidden, float* __restrict__ out) {
    extern __shared__ __align__(128) char smem[];
    const uint32_t sb = smem_u32(smem);
    const int tid = threadIdx.x;
    const int wid = tid >> 5;
    const int lane = tid & 31;
    const int u0 = blockIdx.x * UPB;

    // ---- stage Wh columns as fp16 hi + scaled lo ----
    for (int idx = tid; idx < 24 * 1024; idx += SCTH) {
        int n = idx >> 10, k = idx & 1023;
        int col = (n >> 3) * U_ + u0 + (n & 7);
        float w = Wh[(size_t)k * N3_ + col];
        __half whi = __float2half_rn(w);
        __half wlo = __float2half_rn((w - __half2float(whi)) * WLO_SCALE);
        int off = n * 2064 + k * 2;
        *reinterpret_cast<__half*>(smem + OFF_W + off) = whi;
        *reinterpret_cast<__half*>(smem + OFF_W + WPLANE + off) = wlo;
    }
    float* recs = reinterpret_cast<float*>(smem + OFF_RECS);
    float* bhs = reinterpret_cast<float*>(smem + OFF_BHS);
    if (tid < 24) bhs[tid] = bh[(tid >> 3) * U_ + u0 + (tid & 7)];

    // ---- warp geometry: 4 k-teams x 2 m-halves ----
    const int tm = wid & 3;          // k-team: 32 k per 128-chunk
    const int mh = wid >> 2;         // m-half: rows mh*32 .. +31

    uint32_t b_off[3];
#pragma unroll
    for (int nt = 0; nt < 3; nt++)
        b_off[nt] = (uint32_t)((nt * 8 + (lane & 7)) * 2064 +
                               (((lane >> 3) & 3) << 4));

    // gate mapping & producer slot (fragment-ordered h write)
    const int grow = tid >> 2;
    const int gup = (tid & 3) << 1;
    const int kk = u0 + gup;
    const int slot_p = ((((kk >> 4) * 4 + (grow >> 4)) * 32 +
                         ((grow & 7) * 4 + (((kk & 15) >> 1) & 3))) * 4) +
                       (((grow & 15) >> 3) + 2 * ((kk & 15) >> 3));

    float hprev[2];
    {
        const float2 h2 = *reinterpret_cast<const float2*>(
            &hidden[(size_t)grow * U_ + u0 + gup]);
        hprev[0] = h2.x;
        hprev[1] = h2.y;
    }
    __syncthreads();

    for (int t = 0; t < T_; t++) {
        const int buf = t & 1;
        const uint4* hA0 = reinterpret_cast<const uint4*>(g_hA[buf]);

        // hoisted gate xp loads (independent of h -> issue first)
        float2 xz2, xr2, xh2;
        {
            const float* xp =
                &g_xproj[((size_t)grow * T_ + t) * N3_ + u0 + gup];
            xz2 = __ldg(reinterpret_cast<const float2*>(xp));
            xr2 = __ldg(reinterpret_cast<const float2*>(xp + U_));
            xh2 = __ldg(reinterpret_cast<const float2*>(xp + 2 * U_));
        }

        float acc[2][3][4], acc2[2][3][4];
#pragma unroll
        for (int mt = 0; mt < 2; mt++)
#pragma unroll
            for (int nt = 0; nt < 3; nt++)
#pragma unroll
                for (int j = 0; j < 4; j++) {
                    acc[mt][nt][j] = 0.f;
                    acc2[mt][nt][j] = 0.f;
                }

        uint4 fa[3][4];                       // 2-deep A fragment pipeline
        lda_chunk(fa[0], 0, tm, mh, lane, hA0);
        lda_chunk(fa[1], 1, tm, mh, lane, hA0);

#pragma unroll
        for (int c = 0; c < 8; c++) {
            if (c < 6)
                lda_chunk(fa[(c + 2) % 3], c + 2, tm, mh, lane, hA0);

            const uint32_t bbase =
                sb + OFF_W + (uint32_t)(c * 128 + tm * 32) * 2;
            uint32_t bhf[3][4], blf[3][4];
#pragma unroll
            for (int nt = 0; nt < 3; nt++) {
                ldsm_x4(bhf[nt], bbase + b_off[nt]);
                ldsm_x4(blf[nt], bbase + WPLANE + b_off[nt]);
            }
            const uint4* cur = fa[c % 3];
#pragma unroll
            for (int mtl = 0; mtl < 2; mtl++)
#pragma unroll
                for (int ks = 0; ks < 2; ks++) {
                    const uint32_t* ah =
                        reinterpret_cast<const uint32_t*>(&cur[mtl * 2 + ks]);
#pragma unroll
                    for (int nt = 0; nt < 3; nt++) {
                        mma_f16(acc[mtl][nt], ah, &bhf[nt][ks * 2]);
                        mma_f16(acc2[mtl][nt], ah, &blf[nt][ks * 2]);
                    }
                }
        }

        // write team-partial rec sums (combine scaled-lo): recs[tm][n][row]
        {
            float* recT = recs + tm * RECF;
            int n = 2 * (lane & 3);
            int rowb = mh * 32 + (lane >> 2);
            const float inv = 1.0f / WLO_SCALE;
#pragma unroll
            for (int mt = 0; mt < 2; mt++) {
                int row = rowb + mt * 16;
#pragma unroll
                for (int nt = 0; nt < 3; nt++) {
                    int nb_ = nt * 8 + n;
                    recT[nb_ * 68 + row] =
                        acc[mt][nt][0] + acc2[mt][nt][0] * inv;
                    recT[(nb_ + 1) * 68 + row] =
                        acc[mt][nt][1] + acc2[mt][nt][1] * inv;
                    recT[nb_ * 68 + row + 8] =
                        acc[mt][nt][2] + acc2[mt][nt][2] * inv;
                    recT[(nb_ + 1) * 68 + row + 8] =
                        acc[mt][nt][3] + acc2[mt][nt][3] * inv;
                }
            }
        }
        __syncthreads();

        // gates: each thread does (grow, units gup, gup+1)
        const int nbuf = buf ^ 1;
        float hn[2];
        {
#pragma unroll
            for (int j = 0; j < 2; j++) {
                int uu = gup + j;
                float rz = bhs[uu], rr = bhs[8 + uu], rh = bhs[16 + uu];
#pragma unroll
                for (int tt = 0; tt < 4; tt++) {
                    rz += recs[tt * RECF + uu * 68 + grow];
                    rr += recs[tt * RECF + (8 + uu) * 68 + grow];
                    rh += recs[tt * RECF + (16 + uu) * 68 + grow];
                }
                float xz = j ? xz2.y : xz2.x;
                float xr = j ? xr2.y : xr2.x;
                float xh = j ? xh2.y : xh2.x;
                float z = 1.f / (1.f + __expf(-(xz + rz)));
                float r = 1.f / (1.f + __expf(-(xr + rr)));
                float ca = xh + r * rh;
                float cand = 1.f - 2.f / (__expf(2.f * ca) + 1.f);
                hn[j] = z * hprev[j] + (1.f - z) * cand;
                hprev[j] = hn[j];
            }
            // store fp16 h in fragment order (1 u32: 2 k-adjacent values)
            __half f0 = __float2half_rn(hn[0]);
            __half f1 = __float2half_rn(hn[1]);
            unsigned ph = ((unsigned)__half_as_ushort(f1) << 16) |
                          __half_as_ushort(f0);
            __stcg(&g_hA[nbuf][slot_p], ph);
        }

        // grid barrier; out-stores overlap the spin
        __threadfence();
        __syncthreads();
        if (tid == 0) atomicAdd(&g_bar, 1u);
        {
            float2 o2 = make_float2(hn[0], hn[1]);
            *reinterpret_cast<float2*>(
                &out[((size_t)grow * T_ + t) * U_ + u0 + gup]) = o2;
            if (t == T_ - 1)
                *reinterpret_cast<float2*>(
                    &out[(size_t)B_ * T_ * U_ + (size_t)grow * U_ + u0 + gup]) = o2;
        }
        if (tid == 0) {
            unsigned target = (unsigned)(NBLK * (t + 1));
            while (*((volatile unsigned*)&g_bar) < target) { }
        }
        __syncthreads();
    }
}

// ----------------- launch ---------------------------------------------------
extern "C" void kernel_launch(void* const* d_in, const int* in_sizes, int n_in,
                              void* d_out, int out_size) {
    const int* tokens = (const int*)d_in[0];
    const float* hidden = (const float*)d_in[1];
    const float* emb = (const float*)d_in[2];
    const float* Wx = (const float*)d_in[3];
    const float* bx = (const float*)d_in[4];
    const float* Wh = (const float*)d_in[5];
    const float* bh = (const float*)d_in[6];
    float* out = (float*)d_out;
    (void)in_sizes; (void)n_in; (void)out_size;

    cudaFuncSetAttribute(k_scan, cudaFuncAttributeMaxDynamicSharedMemorySize,
                         SCAN_SMEM);
    cudaFuncSetAttribute(k_xproj_tc, cudaFuncAttributeMaxDynamicSharedMemorySize,
                         XP_SMEM);

    k_init<<<(B_ * U_ + 255) / 256, 256>>>(hidden);
    k_prep<<<1024, 256>>>(emb, Wx);
    dim3 gx(N3_ / 64, (B_ * T_) / 128);
    k_xproj_tc<<<gx, 256, XP_SMEM>>>(tokens, bx);
    k_scan<<<NBLK, SCTH, SCAN_SMEM>>>(Wh, bh, hidden, out);
}